// round 7
// baseline (speedup 1.0000x reference)
#include <cuda_runtime.h>
#include <cuda_bf16.h>
#include <stdint.h>
#include <math.h>

#define BATCH 4
#define SEQ   2048
#define NDIM  768
#define HDIM  768
#define MTOT  (BATCH * SEQ)

typedef __nv_bfloat16 bf16;

// ------------------------- scratch (allocation-free) ------------------------
__device__ __align__(16) bf16  g_xh[MTOT * NDIM];
__device__ __align__(16) bf16  g_xl[MTOT * NDIM];
__device__ __align__(16) bf16  g_wqh[HDIM * NDIM];
__device__ __align__(16) bf16  g_wql[HDIM * NDIM];
__device__ __align__(16) bf16  g_wkh[HDIM * NDIM];
__device__ __align__(16) bf16  g_wkl[HDIM * NDIM];
__device__ __align__(16) bf16  g_wvh[HDIM * NDIM];
__device__ __align__(16) bf16  g_wvl[HDIM * NDIM];
__device__ __align__(16) bf16  g_woh[NDIM * HDIM];
__device__ __align__(16) bf16  g_wol[NDIM * HDIM];
__device__ __align__(16) bf16  g_qh[MTOT * HDIM];
__device__ __align__(16) bf16  g_ql[MTOT * HDIM];
__device__ __align__(16) bf16  g_kh[MTOT * HDIM];
__device__ __align__(16) bf16  g_kl[MTOT * HDIM];
__device__ __align__(16) float g_v [MTOT * HDIM];
__device__ __align__(16) bf16  g_vth[(long long)BATCH * HDIM * SEQ];
__device__ __align__(16) bf16  g_vtl[(long long)BATCH * HDIM * SEQ];
__device__ __align__(16) float g_s [(long long)BATCH * SEQ * SEQ];
__device__ __align__(16) bf16  g_sh[(long long)BATCH * SEQ * SEQ];
__device__ __align__(16) bf16  g_sl[(long long)BATCH * SEQ * SEQ];
__device__ __align__(16) bf16  g_yh[MTOT * HDIM];
__device__ __align__(16) bf16  g_yl[MTOT * HDIM];

// ------------------------------ helpers -------------------------------------
__device__ __forceinline__ void mma16816(float* d, const uint32_t* a, const uint32_t* b)
{
    asm volatile(
        "mma.sync.aligned.m16n8k16.row.col.f32.bf16.bf16.f32 "
        "{%0,%1,%2,%3},{%4,%5,%6,%7},{%8,%9},{%0,%1,%2,%3};\n"
        : "+f"(d[0]), "+f"(d[1]), "+f"(d[2]), "+f"(d[3])
        : "r"(a[0]), "r"(a[1]), "r"(a[2]), "r"(a[3]), "r"(b[0]), "r"(b[1]));
}

__device__ __forceinline__ void ldsm_x4(uint32_t* r, uint32_t addr)
{
    asm volatile("ldmatrix.sync.aligned.m8n8.x4.shared.b16 {%0,%1,%2,%3}, [%4];"
                 : "=r"(r[0]), "=r"(r[1]), "=r"(r[2]), "=r"(r[3]) : "r"(addr));
}

__device__ __forceinline__ void split1(float x, bf16& h, bf16& l)
{
    h = __float2bfloat16(x);
    l = __float2bfloat16(x - __bfloat162float(h));
}

__device__ __forceinline__ void cpa16(uint32_t dst, const void* src)
{
    asm volatile("cp.async.cg.shared.global [%0], [%1], 16;\n" :: "r"(dst), "l"(src));
}
__device__ __forceinline__ void cpa_commit() { asm volatile("cp.async.commit_group;\n"); }
template <int N>
__device__ __forceinline__ void cpa_wait() { asm volatile("cp.async.wait_group %0;\n" :: "n"(N)); }

// smem geometry (uint32 words). Row = 16 data words (32 bf16 of k) + 4 pad.
#define RSTRIDE 20
#define PLANE_W (128 * RSTRIDE)              // 2560 words = 10240 B
#define PLANE_B (PLANE_W * 4)
#define STAGE_B (4 * PLANE_B)                // AsH AsL BsH BsL = 40960 B
#define NSTAGE  3
#define SMEM_BYTES (NSTAGE * STAGE_B)        // 122880

// ---------------------------------------------------------------------------
// Split-bf16 tensor-core GEMM: C = A * B^T (+bias)
//   A: [M,K] hi/lo bf16 planes; B: [N,K] hi/lo bf16 planes (row-major)
// EPI=0: fp32 Cf.  EPI=1: split bf16 Ch/Cl.
// CTA tile 128x128, BK=32, 512 threads, 16 warps of 32x32.
// 3-stage cp.async ring, ONE __syncthreads per k-tile, whole-tile fragment
// residency (8 A-ldsm.x4 + 8 B-ldsm.x4 per warp per tile, then 48 HMMA).
// ---------------------------------------------------------------------------
template <int EPI>
__global__ void __launch_bounds__(512, 1) bf16s_gemm(
    const bf16* __restrict__ Ah, const bf16* __restrict__ Al,
    const bf16* __restrict__ Bh, const bf16* __restrict__ Bl,
    const float* __restrict__ bias,
    float* __restrict__ Cf, bf16* __restrict__ Ch, bf16* __restrict__ Cl,
    int M, int N, int K,
    long long sA, long long sB, long long sC)
{
    extern __shared__ uint32_t smem[];

    Ah += (long long)blockIdx.z * sA;  Al += (long long)blockIdx.z * sA;
    Bh += (long long)blockIdx.z * sB;  Bl += (long long)blockIdx.z * sB;
    if (EPI == 0) Cf += (long long)blockIdx.z * sC;
    else { Ch += (long long)blockIdx.z * sC; Cl += (long long)blockIdx.z * sC; }

    const int tid  = threadIdx.x;
    const int lane = tid & 31;
    const int warp = tid >> 5;
    const int bm = blockIdx.y * 128;
    const int bn = blockIdx.x * 128;
    const int wm = (warp & 3) * 32;      // warp-tile m origin (0..96)
    const int wn = (warp >> 2) * 32;     // warp-tile n origin (0..96)
    const int r = lane >> 2;
    const int c = lane & 3;

    // ---- loader: 512 threads, each 1x16B chunk per plane per stage ----
    const int lrow = tid >> 2;           // 0..127
    const int c16  = tid & 3;            // 16B chunk in 64B row
    const bf16* gAh = Ah + (long long)(bm + lrow) * K + c16 * 8;
    const bf16* gAl = Al + (long long)(bm + lrow) * K + c16 * 8;
    const bf16* gBh = Bh + (long long)(bn + lrow) * K + c16 * 8;
    const bf16* gBl = Bl + (long long)(bn + lrow) * K + c16 * 8;

    uint32_t smem_u32;
    asm("{ .reg .u64 t; cvta.to.shared.u64 t, %1; cvt.u32.u64 %0, t; }"
        : "=r"(smem_u32) : "l"(smem));
    const uint32_t dst_base = smem_u32 + (lrow * RSTRIDE + 4 * c16) * 4;

    auto load_stage = [&](int s, int kt) {
        const uint32_t d = dst_base + s * STAGE_B;
        const int k0 = kt * 32;
        cpa16(d,                gAh + k0);
        cpa16(d + PLANE_B,      gAl + k0);
        cpa16(d + 2 * PLANE_B,  gBh + k0);
        cpa16(d + 3 * PLANE_B,  gBl + k0);
    };

    // ---- ldmatrix lane address offsets (bytes, within a plane) ----
    // A x4 (per mi, per ks): lanes 0-15 rows wm+mi*16+(lane&15) @k0,
    //                        lanes 16-31 same rows @k0+8  -> frag {a0..a3}
    const uint32_t aOff = (uint32_t)((wm + (lane & 15)) * RSTRIDE + ((lane >> 4) << 2)) << 2;
    // B x4 (per ni, both ks): lanes 8j..8j+7 rows wn+ni*8+(lane&7) @k = j*8
    //   -> r0,r1 = ks0 frag, r2,r3 = ks1 frag
    const uint32_t bOff = (uint32_t)((wn + (lane & 7)) * RSTRIDE + ((lane >> 3) << 2)) << 2;

    float acc[2][4][4];
    #pragma unroll
    for (int i = 0; i < 2; i++)
        #pragma unroll
        for (int j = 0; j < 4; j++)
            #pragma unroll
            for (int e = 0; e < 4; e++) acc[i][j][e] = 0.f;

    const int T = K / 32;

    // prologue: prefetch stages 0,1
    load_stage(0, 0); cpa_commit();
    load_stage(1, 1); cpa_commit();

    for (int t = 0; t < T; t++) {
        const int s = t % NSTAGE;
        cpa_wait<1>();
        __syncthreads();     // stage s data visible to all; all done with prior occupant

        if (t + 2 < T) load_stage((t + 2) % NSTAGE, t + 2);
        cpa_commit();

        const uint32_t sb = smem_u32 + s * STAGE_B;
        const uint32_t aBaseH = sb + aOff;
        const uint32_t aBaseL = aBaseH + PLANE_B;
        const uint32_t bBaseH = sb + 2 * PLANE_B + bOff;
        const uint32_t bBaseL = bBaseH + PLANE_B;

        // ---- load ALL fragments for this tile ----
        uint32_t aH[2][2][4], aL[2][2][4];   // [mi][ks][4]
        uint32_t bF[4][2][2][2];             // [ni][plane][ks][2]
        #pragma unroll
        for (int mi = 0; mi < 2; mi++) {
            #pragma unroll
            for (int ks = 0; ks < 2; ks++) {
                const uint32_t o = mi * (16 * RSTRIDE * 4) + ks * 32;
                ldsm_x4(aH[mi][ks], aBaseH + o);
                ldsm_x4(aL[mi][ks], aBaseL + o);
            }
        }
        #pragma unroll
        for (int ni = 0; ni < 4; ni++) {
            const uint32_t o = ni * (8 * RSTRIDE * 4);
            uint32_t rh[4], rl[4];
            ldsm_x4(rh, bBaseH + o);
            ldsm_x4(rl, bBaseL + o);
            bF[ni][0][0][0] = rh[0]; bF[ni][0][0][1] = rh[1];
            bF[ni][0][1][0] = rh[2]; bF[ni][0][1][1] = rh[3];
            bF[ni][1][0][0] = rl[0]; bF[ni][1][0][1] = rl[1];
            bF[ni][1][1][0] = rl[2]; bF[ni][1][1][1] = rl[3];
        }

        // ---- 48 back-to-back MMAs ----
        #pragma unroll
        for (int ks = 0; ks < 2; ks++)
            #pragma unroll
            for (int mi = 0; mi < 2; mi++)
                #pragma unroll
                for (int ni = 0; ni < 4; ni++) {
                    mma16816(acc[mi][ni], aH[mi][ks], bF[ni][0][ks]);
                    mma16816(acc[mi][ni], aH[mi][ks], bF[ni][1][ks]);
                    mma16816(acc[mi][ni], aL[mi][ks], bF[ni][0][ks]);
                }
    }

    // ---------------- epilogue ----------------
    #pragma unroll
    for (int mi = 0; mi < 2; mi++)
        #pragma unroll
        for (int ni = 0; ni < 4; ni++) {
            const int row = bm + wm + mi * 16 + r;
            const int col = bn + wn + ni * 8 + 2 * c;
            float v00 = acc[mi][ni][0], v01 = acc[mi][ni][1];
            float v10 = acc[mi][ni][2], v11 = acc[mi][ni][3];
            if (bias) {
                const float b0 = bias[col], b1 = bias[col + 1];
                v00 += b0; v01 += b1; v10 += b0; v11 += b1;
            }
            if (EPI == 0) {
                *reinterpret_cast<float2*>(Cf + (long long)row * N + col)
                    = make_float2(v00, v01);
                *reinterpret_cast<float2*>(Cf + (long long)(row + 8) * N + col)
                    = make_float2(v10, v11);
            } else {
                bf16 h0, l0, h1, l1;
                split1(v00, h0, l0); split1(v01, h1, l1);
                *reinterpret_cast<__nv_bfloat162*>(Ch + (long long)row * N + col)
                    = __halves2bfloat162(h0, h1);
                *reinterpret_cast<__nv_bfloat162*>(Cl + (long long)row * N + col)
                    = __halves2bfloat162(l0, l1);
                split1(v10, h0, l0); split1(v11, h1, l1);
                *reinterpret_cast<__nv_bfloat162*>(Ch + (long long)(row + 8) * N + col)
                    = __halves2bfloat162(h0, h1);
                *reinterpret_cast<__nv_bfloat162*>(Cl + (long long)(row + 8) * N + col)
                    = __halves2bfloat162(l0, l1);
            }
        }
}

// ---------------------------------------------------------------------------
__global__ void __launch_bounds__(256) split_f32(
    const float* __restrict__ in, bf16* __restrict__ h, bf16* __restrict__ l, int n4)
{
    for (int i = blockIdx.x * blockDim.x + threadIdx.x; i < n4;
         i += gridDim.x * blockDim.x) {
        float4 v = reinterpret_cast<const float4*>(in)[i];
        bf16 h0,l0,h1,l1,h2,l2,h3,l3;
        split1(v.x, h0, l0); split1(v.y, h1, l1);
        split1(v.z, h2, l2); split1(v.w, h3, l3);
        reinterpret_cast<__nv_bfloat162*>(h)[2 * i]     = __halves2bfloat162(h0, h1);
        reinterpret_cast<__nv_bfloat162*>(h)[2 * i + 1] = __halves2bfloat162(h2, h3);
        reinterpret_cast<__nv_bfloat162*>(l)[2 * i]     = __halves2bfloat162(l0, l1);
        reinterpret_cast<__nv_bfloat162*>(l)[2 * i + 1] = __halves2bfloat162(l2, l3);
    }
}

// ---------------------------------------------------------------------------
__global__ void __launch_bounds__(256) transpose_split(
    const float* __restrict__ V, bf16* __restrict__ Th, bf16* __restrict__ Tl)
{
    __shared__ float tile[32][33];
    const int b  = blockIdx.z;
    const int h0 = blockIdx.x * 32;
    const int s0 = blockIdx.y * 32;
    const int tx = threadIdx.x & 31;
    const int ty = threadIdx.x >> 5;

    #pragma unroll
    for (int j = 0; j < 4; j++) {
        const int s = s0 + ty + j * 8;
        tile[ty + j * 8][tx] = V[(long long)(b * SEQ + s) * HDIM + h0 + tx];
    }
    __syncthreads();
    #pragma unroll
    for (int j = 0; j < 4; j++) {
        const int h = h0 + ty + j * 8;
        const float v = tile[tx][ty + j * 8];
        bf16 hi, lo; split1(v, hi, lo);
        const long long o = ((long long)b * HDIM + h) * SEQ + s0 + tx;
        Th[o] = hi; Tl[o] = lo;
    }
}

// ---------------------------------------------------------------------------
__global__ void __launch_bounds__(256) softmax_split(
    const float* __restrict__ S, bf16* __restrict__ Ph, bf16* __restrict__ Pl)
{
    __shared__ float buf[SEQ];
    __shared__ float red[8];

    const int tid = threadIdx.x;
    const float2* row2 = reinterpret_cast<const float2*>(S + (long long)blockIdx.x * SEQ);
    float2* b2 = reinterpret_cast<float2*>(buf);

    float m = -1e30f;
    #pragma unroll
    for (int j = 0; j < 4; j++) {
        float2 f = row2[tid + j * 256];
        b2[tid + j * 256] = f;
        m = fmaxf(m, fmaxf(f.x, f.y));
    }
    #pragma unroll
    for (int o = 16; o > 0; o >>= 1)
        m = fmaxf(m, __shfl_xor_sync(0xffffffffu, m, o));
    if ((tid & 31) == 0) red[tid >> 5] = m;
    __syncthreads();
    float bmax = red[0];
    #pragma unroll
    for (int w = 1; w < 8; w++) bmax = fmaxf(bmax, red[w]);
    __syncthreads();

    float s = 0.f;
    #pragma unroll
    for (int j = 0; j < 4; j++) {
        float2 f = b2[tid + j * 256];
        f.x = __expf(f.x - bmax);
        f.y = __expf(f.y - bmax);
        b2[tid + j * 256] = f;
        s += f.x + f.y;
    }
    #pragma unroll
    for (int o = 16; o > 0; o >>= 1)
        s += __shfl_xor_sync(0xffffffffu, s, o);
    if ((tid & 31) == 0) red[tid >> 5] = s;
    __syncthreads();
    float tot = 0.f;
    #pragma unroll
    for (int w = 0; w < 8; w++) tot += red[w];
    const float inv = 1.f / tot;

    __nv_bfloat162* ph2 = reinterpret_cast<__nv_bfloat162*>(Ph) + (long long)blockIdx.x * (SEQ / 2);
    __nv_bfloat162* pl2 = reinterpret_cast<__nv_bfloat162*>(Pl) + (long long)blockIdx.x * (SEQ / 2);
    #pragma unroll
    for (int j = 0; j < 4; j++) {
        float2 f = b2[tid + j * 256];
        const float p0 = f.x * inv, p1 = f.y * inv;
        bf16 h0,l0,h1,l1;
        split1(p0, h0, l0); split1(p1, h1, l1);
        ph2[tid + j * 256] = __halves2bfloat162(h0, h1);
        pl2[tid + j * 256] = __halves2bfloat162(l0, l1);
    }
}

// ---------------------------------------------------------------------------
extern "C" void kernel_launch(void* const* d_in, const int* in_sizes, int n_in,
                              void* d_out, int out_size)
{
    const float* x  = (const float*)d_in[0];
    const float* wq = (const float*)d_in[1];
    const float* bq = (const float*)d_in[2];
    const float* wk = (const float*)d_in[3];
    const float* bk = (const float*)d_in[4];
    const float* wv = (const float*)d_in[5];
    const float* bv = (const float*)d_in[6];
    const float* wo = (const float*)d_in[7];
    const float* bo = (const float*)d_in[8];
    float* out = (float*)d_out;

    static bool attr_done = false;
    if (!attr_done) {
        cudaFuncSetAttribute(bf16s_gemm<0>, cudaFuncAttributeMaxDynamicSharedMemorySize, SMEM_BYTES);
        cudaFuncSetAttribute(bf16s_gemm<1>, cudaFuncAttributeMaxDynamicSharedMemorySize, SMEM_BYTES);
        attr_done = true;
    }

    bf16 *xh,*xl,*wqh,*wql,*wkh,*wkl,*wvh,*wvl,*woh,*wol;
    bf16 *qh,*ql,*kh,*kl,*vth,*vtl,*sh,*sl,*yh,*yl;
    float *v, *s;
    cudaGetSymbolAddress((void**)&xh, g_xh);   cudaGetSymbolAddress((void**)&xl, g_xl);
    cudaGetSymbolAddress((void**)&wqh, g_wqh); cudaGetSymbolAddress((void**)&wql, g_wql);
    cudaGetSymbolAddress((void**)&wkh, g_wkh); cudaGetSymbolAddress((void**)&wkl, g_wkl);
    cudaGetSymbolAddress((void**)&wvh, g_wvh); cudaGetSymbolAddress((void**)&wvl, g_wvl);
    cudaGetSymbolAddress((void**)&woh, g_woh); cudaGetSymbolAddress((void**)&wol, g_wol);
    cudaGetSymbolAddress((void**)&qh, g_qh);   cudaGetSymbolAddress((void**)&ql, g_ql);
    cudaGetSymbolAddress((void**)&kh, g_kh);   cudaGetSymbolAddress((void**)&kl, g_kl);
    cudaGetSymbolAddress((void**)&v, g_v);
    cudaGetSymbolAddress((void**)&vth, g_vth); cudaGetSymbolAddress((void**)&vtl, g_vtl);
    cudaGetSymbolAddress((void**)&s, g_s);
    cudaGetSymbolAddress((void**)&sh, g_sh);   cudaGetSymbolAddress((void**)&sl, g_sl);
    cudaGetSymbolAddress((void**)&yh, g_yh);   cudaGetSymbolAddress((void**)&yl, g_yl);

    const dim3 blk(512);
    const dim3 blk256(256);

    // 0) split x and weights into hi/lo bf16 planes
    split_f32<<<512, blk256>>>(x,  xh,  xl,  MTOT * NDIM / 4);
    split_f32<<<128, blk256>>>(wq, wqh, wql, HDIM * NDIM / 4);
    split_f32<<<128, blk256>>>(wk, wkh, wkl, HDIM * NDIM / 4);
    split_f32<<<128, blk256>>>(wv, wvh, wvl, HDIM * NDIM / 4);
    split_f32<<<128, blk256>>>(wo, woh, wol, NDIM * HDIM / 4);

    // 1) projections
    {
        dim3 grid(HDIM / 128, MTOT / 128, 1);
        bf16s_gemm<1><<<grid, blk, SMEM_BYTES>>>(xh, xl, wqh, wql, bq,
                                                 nullptr, qh, ql, MTOT, HDIM, NDIM, 0, 0, 0);
        bf16s_gemm<1><<<grid, blk, SMEM_BYTES>>>(xh, xl, wkh, wkl, bk,
                                                 nullptr, kh, kl, MTOT, HDIM, NDIM, 0, 0, 0);
        bf16s_gemm<0><<<grid, blk, SMEM_BYTES>>>(xh, xl, wvh, wvl, bv,
                                                 v, nullptr, nullptr, MTOT, HDIM, NDIM, 0, 0, 0);
    }
    {
        dim3 grid(HDIM / 32, SEQ / 32, BATCH);
        transpose_split<<<grid, blk256>>>(v, vth, vtl);
    }

    // 2) scores = Q K^T
    {
        dim3 grid(SEQ / 128, SEQ / 128, BATCH);
        bf16s_gemm<0><<<grid, blk, SMEM_BYTES>>>(qh, ql, kh, kl, nullptr,
                                                 s, nullptr, nullptr, SEQ, SEQ, HDIM,
                                                 (long long)SEQ * HDIM,
                                                 (long long)SEQ * HDIM,
                                                 (long long)SEQ * SEQ);
    }

    // 3) softmax -> split bf16 probs
    softmax_split<<<BATCH * SEQ, blk256>>>(s, sh, sl);

    // 4) y = P V  (B operand = V^T planes [HDIM, SEQ])
    {
        dim3 grid(HDIM / 128, SEQ / 128, BATCH);
        bf16s_gemm<1><<<grid, blk, SMEM_BYTES>>>(sh, sl, vth, vtl, nullptr,
                                                 nullptr, yh, yl, SEQ, HDIM, SEQ,
                                                 (long long)SEQ * SEQ,
                                                 (long long)HDIM * SEQ,
                                                 (long long)SEQ * HDIM);
    }

    // 5) out = Y Wo^T + bo
    {
        dim3 grid(NDIM / 128, MTOT / 128, 1);
        bf16s_gemm<0><<<grid, blk, SMEM_BYTES>>>(yh, yl, woh, wol, bo,
                                                 out, nullptr, nullptr, MTOT, NDIM, HDIM, 0, 0, 0);
    }
}

// round 8
// speedup vs baseline: 1.1624x; 1.1624x over previous
#include <cuda_runtime.h>
#include <cuda_bf16.h>
#include <stdint.h>
#include <math.h>

#define BATCH 4
#define SEQ   2048
#define NDIM  768
#define HDIM  768
#define MTOT  (BATCH * SEQ)

typedef __nv_bfloat16 bf16;

// ------------------------- scratch (allocation-free) ------------------------
__device__ __align__(16) bf16  g_xh[MTOT * NDIM];
__device__ __align__(16) bf16  g_xl[MTOT * NDIM];
__device__ __align__(16) bf16  g_wch[3 * HDIM * NDIM];   // concat wq|wk|wv planes
__device__ __align__(16) bf16  g_wcl[3 * HDIM * NDIM];
__device__ __align__(16) bf16  g_woh[NDIM * HDIM];
__device__ __align__(16) bf16  g_wol[NDIM * HDIM];
__device__ __align__(16) bf16  g_qh[MTOT * HDIM];
__device__ __align__(16) bf16  g_ql[MTOT * HDIM];
__device__ __align__(16) bf16  g_kh[MTOT * HDIM];
__device__ __align__(16) bf16  g_kl[MTOT * HDIM];
__device__ __align__(16) bf16  g_vh[MTOT * HDIM];
__device__ __align__(16) bf16  g_vl[MTOT * HDIM];
__device__ __align__(16) bf16  g_vth[(long long)BATCH * HDIM * SEQ];
__device__ __align__(16) bf16  g_vtl[(long long)BATCH * HDIM * SEQ];
__device__ __align__(16) float g_s [(long long)BATCH * SEQ * SEQ];
__device__ __align__(16) bf16  g_sh[(long long)BATCH * SEQ * SEQ];
__device__ __align__(16) bf16  g_sl[(long long)BATCH * SEQ * SEQ];
__device__ __align__(16) bf16  g_yh[MTOT * HDIM];
__device__ __align__(16) bf16  g_yl[MTOT * HDIM];

// ------------------------------ helpers -------------------------------------
__device__ __forceinline__ void mma16816(float* d, const uint32_t* a, const uint32_t* b)
{
    asm volatile(
        "mma.sync.aligned.m16n8k16.row.col.f32.bf16.bf16.f32 "
        "{%0,%1,%2,%3},{%4,%5,%6,%7},{%8,%9},{%0,%1,%2,%3};\n"
        : "+f"(d[0]), "+f"(d[1]), "+f"(d[2]), "+f"(d[3])
        : "r"(a[0]), "r"(a[1]), "r"(a[2]), "r"(a[3]), "r"(b[0]), "r"(b[1]));
}

__device__ __forceinline__ void ldsm_x4(uint32_t* r, uint32_t addr)
{
    asm volatile("ldmatrix.sync.aligned.m8n8.x4.shared.b16 {%0,%1,%2,%3}, [%4];"
                 : "=r"(r[0]), "=r"(r[1]), "=r"(r[2]), "=r"(r[3]) : "r"(addr));
}

__device__ __forceinline__ void split1(float x, bf16& h, bf16& l)
{
    h = __float2bfloat16(x);
    l = __float2bfloat16(x - __bfloat162float(h));
}

__device__ __forceinline__ void cpa16(uint32_t dst, const void* src)
{
    asm volatile("cp.async.cg.shared.global [%0], [%1], 16;\n" :: "r"(dst), "l"(src));
}
__device__ __forceinline__ void cpa_commit() { asm volatile("cp.async.commit_group;\n"); }
template <int N>
__device__ __forceinline__ void cpa_wait() { asm volatile("cp.async.wait_group %0;\n" :: "n"(N)); }

// smem geometry (uint32 words). Row = 16 data words (32 bf16 of k) + 4 pad.
#define RSTRIDE 20
#define PLANE_W (128 * RSTRIDE)              // 2560 words = 10240 B
#define PLANE_B (PLANE_W * 4)
#define STAGE_B (4 * PLANE_B)                // AsH AsL BsH BsL = 40960 B
#define SMEM_BYTES (2 * STAGE_B)             // 81920 (2 stages)

// ---------------------------------------------------------------------------
// Split-bf16 tensor-core GEMM: C = A * B^T (+bias)
//   A: [M,K] hi/lo bf16 planes; B: [N,K] hi/lo bf16 planes (row-major)
// EPI=0: fp32 Cf (row stride ldc).
// EPI=1: split bf16 Ch/Cl (row stride ldc).
// EPI=2: QKV-fused — B is concat [2304,K]; N-segment routes to (Ch,Cl)/(C2..)/(C3..)
//        with per-segment bias0/1/2; each dest row stride 768.
// CTA tile 128x128, BK=32, 8 warps of 64x32, 2-stage cp.async, ldmatrix frags.
// ---------------------------------------------------------------------------
template <int EPI>
__global__ void __launch_bounds__(256, 2) bf16s_gemm(
    const bf16* __restrict__ Ah, const bf16* __restrict__ Al,
    const bf16* __restrict__ Bh, const bf16* __restrict__ Bl,
    const float* __restrict__ bias0, const float* __restrict__ bias1,
    const float* __restrict__ bias2,
    float* __restrict__ Cf,
    bf16* __restrict__ Ch, bf16* __restrict__ Cl,
    bf16* __restrict__ C2h, bf16* __restrict__ C2l,
    bf16* __restrict__ C3h, bf16* __restrict__ C3l,
    int M, int N, int K, int ldc,
    long long sA, long long sB, long long sC)
{
    extern __shared__ uint32_t smem[];

    Ah += (long long)blockIdx.z * sA;  Al += (long long)blockIdx.z * sA;
    Bh += (long long)blockIdx.z * sB;  Bl += (long long)blockIdx.z * sB;
    if (EPI == 0) Cf += (long long)blockIdx.z * sC;
    else if (EPI == 1) { Ch += (long long)blockIdx.z * sC; Cl += (long long)blockIdx.z * sC; }

    const int tid  = threadIdx.x;
    const int lane = tid & 31;
    const int warp = tid >> 5;
    const int bm = blockIdx.y * 128;
    const int bn = blockIdx.x * 128;
    const int wm = (warp & 1) * 64;
    const int wn = (warp >> 1) * 32;
    const int r = lane >> 2;
    const int c = lane & 3;

    // ---- loader mapping: thread -> row=tid/2, two 16B chunks per plane ----
    const int ld_row = tid >> 1;
    const int ld_c0  = (tid & 1) * 2;
    const bf16* pAh = Ah + (long long)(bm + ld_row) * K + ld_c0 * 8;
    const bf16* pAl = Al + (long long)(bm + ld_row) * K + ld_c0 * 8;
    const bf16* pBh = Bh + (long long)(bn + ld_row) * K + ld_c0 * 8;
    const bf16* pBl = Bl + (long long)(bn + ld_row) * K + ld_c0 * 8;

    uint32_t smem_u32;
    asm("{ .reg .u64 t; cvta.to.shared.u64 t, %1; cvt.u32.u64 %0, t; }"
        : "=r"(smem_u32) : "l"(smem));
    const uint32_t dst_base = smem_u32 + (ld_row * RSTRIDE + 4 * ld_c0) * 4;

    auto load_stage = [&](int stage, int k0) {
        const uint32_t d = dst_base + stage * STAGE_B;
        cpa16(d,                pAh + k0);
        cpa16(d + 16,           pAh + k0 + 8);
        cpa16(d + PLANE_B,      pAl + k0);
        cpa16(d + PLANE_B + 16, pAl + k0 + 8);
        cpa16(d + 2 * PLANE_B,      pBh + k0);
        cpa16(d + 2 * PLANE_B + 16, pBh + k0 + 8);
        cpa16(d + 3 * PLANE_B,      pBl + k0);
        cpa16(d + 3 * PLANE_B + 16, pBl + k0 + 8);
    };

    // ---- ldmatrix lane address offsets (bytes, within a plane) ----
    // A .x4: lanes 0-15 rows wm+(lane&15) @k0, lanes 16-31 same rows @k0+8
    const uint32_t aOff = (((wm + (lane & 15)) * RSTRIDE + ((lane >> 4) << 2)) << 2);
    // B .x4 (ni-pair): lanes 0-7 rows wn+(l&7) @k0 | 8-15 @k+8 |
    //                  16-23 rows wn+8+(l&7) @k0 | 24-31 @k+8
    const uint32_t bOff = (((wn + (lane & 7) + ((lane >> 4) << 3)) * RSTRIDE
                            + (((lane >> 3) & 1) << 2)) << 2);

    float acc[4][4][4];
    #pragma unroll
    for (int i = 0; i < 4; i++)
        #pragma unroll
        for (int j = 0; j < 4; j++)
            #pragma unroll
            for (int e = 0; e < 4; e++) acc[i][j][e] = 0.f;

    const int T = K / 32;

    load_stage(0, 0);  cpa_commit();
    if (T > 1) load_stage(1, 32);
    cpa_commit();

    for (int t = 0; t < T; t++) {
        cpa_wait<1>();
        __syncthreads();

        const uint32_t stage_base = smem_u32 + (t & 1) * STAGE_B;
        const uint32_t aBaseH = stage_base + aOff;
        const uint32_t aBaseL = aBaseH + PLANE_B;
        const uint32_t bBaseH = stage_base + 2 * PLANE_B + bOff;
        const uint32_t bBaseL = bBaseH + PLANE_B;

        #pragma unroll
        for (int ks = 0; ks < 2; ks++) {
            const uint32_t kb = ks * 32;   // +16 k elements = 32 bytes
            uint32_t aH[4][4], aL[4][4], bH[4][2], bL[4][2];
            #pragma unroll
            for (int mi = 0; mi < 4; mi++) {
                ldsm_x4(aH[mi], aBaseH + mi * (16 * RSTRIDE * 4) + kb);
                ldsm_x4(aL[mi], aBaseL + mi * (16 * RSTRIDE * 4) + kb);
            }
            #pragma unroll
            for (int np = 0; np < 2; np++) {
                uint32_t th[4], tl[4];
                ldsm_x4(th, bBaseH + np * (16 * RSTRIDE * 4) + kb);
                ldsm_x4(tl, bBaseL + np * (16 * RSTRIDE * 4) + kb);
                bH[2*np][0] = th[0]; bH[2*np][1] = th[1];
                bH[2*np+1][0] = th[2]; bH[2*np+1][1] = th[3];
                bL[2*np][0] = tl[0]; bL[2*np][1] = tl[1];
                bL[2*np+1][0] = tl[2]; bL[2*np+1][1] = tl[3];
            }
            #pragma unroll
            for (int mi = 0; mi < 4; mi++)
                #pragma unroll
                for (int ni = 0; ni < 4; ni++) {
                    mma16816(acc[mi][ni], aH[mi], bH[ni]);
                    mma16816(acc[mi][ni], aH[mi], bL[ni]);
                    mma16816(acc[mi][ni], aL[mi], bH[ni]);
                }
        }
        __syncthreads();

        if (t + 2 < T) load_stage(t & 1, (t + 2) * 32);
        cpa_commit();
    }

    // ---------------- epilogue ----------------
    // dest routing (per-CTA uniform for EPI==2)
    const float* bias = bias0;
    bf16* dh = Ch; bf16* dl = Cl;
    int cb = bn;           // local column base within dest
    int stride = ldc;
    if (EPI == 2) {
        const int seg = bn / 768;
        cb = bn - seg * 768;
        stride = 768;
        if (seg == 1) { bias = bias1; dh = C2h; dl = C2l; }
        else if (seg == 2) { bias = bias2; dh = C3h; dl = C3l; }
    }

    #pragma unroll
    for (int mi = 0; mi < 4; mi++)
        #pragma unroll
        for (int ni = 0; ni < 4; ni++) {
            const int row = bm + wm + mi * 16 + r;
            const int col = cb + wn + ni * 8 + 2 * c;
            float v00 = acc[mi][ni][0], v01 = acc[mi][ni][1];
            float v10 = acc[mi][ni][2], v11 = acc[mi][ni][3];
            if (bias) {
                const float b0 = bias[col], b1 = bias[col + 1];
                v00 += b0; v01 += b1; v10 += b0; v11 += b1;
            }
            if (EPI == 0) {
                *reinterpret_cast<float2*>(Cf + (long long)row * stride + col)
                    = make_float2(v00, v01);
                *reinterpret_cast<float2*>(Cf + (long long)(row + 8) * stride + col)
                    = make_float2(v10, v11);
            } else {
                bf16 h0, l0, h1, l1;
                split1(v00, h0, l0); split1(v01, h1, l1);
                *reinterpret_cast<__nv_bfloat162*>(dh + (long long)row * stride + col)
                    = __halves2bfloat162(h0, h1);
                *reinterpret_cast<__nv_bfloat162*>(dl + (long long)row * stride + col)
                    = __halves2bfloat162(l0, l1);
                split1(v10, h0, l0); split1(v11, h1, l1);
                *reinterpret_cast<__nv_bfloat162*>(dh + (long long)(row + 8) * stride + col)
                    = __halves2bfloat162(h0, h1);
                *reinterpret_cast<__nv_bfloat162*>(dl + (long long)(row + 8) * stride + col)
                    = __halves2bfloat162(l0, l1);
            }
        }
}

// ---------------------------------------------------------------------------
__global__ void __launch_bounds__(256) split_f32(
    const float* __restrict__ in, bf16* __restrict__ h, bf16* __restrict__ l, int n4)
{
    for (int i = blockIdx.x * blockDim.x + threadIdx.x; i < n4;
         i += gridDim.x * blockDim.x) {
        float4 v = reinterpret_cast<const float4*>(in)[i];
        bf16 h0,l0,h1,l1,h2,l2,h3,l3;
        split1(v.x, h0, l0); split1(v.y, h1, l1);
        split1(v.z, h2, l2); split1(v.w, h3, l3);
        reinterpret_cast<__nv_bfloat162*>(h)[2 * i]     = __halves2bfloat162(h0, h1);
        reinterpret_cast<__nv_bfloat162*>(h)[2 * i + 1] = __halves2bfloat162(h2, h3);
        reinterpret_cast<__nv_bfloat162*>(l)[2 * i]     = __halves2bfloat162(l0, l1);
        reinterpret_cast<__nv_bfloat162*>(l)[2 * i + 1] = __halves2bfloat162(l2, l3);
    }
}

// ---------------------------------------------------------------------------
// V transpose: v planes [B*SEQ, HDIM] hi/lo -> VT planes [B, HDIM, SEQ]
// (fp32 value reconstructed as hi+lo, then re-split)
// ---------------------------------------------------------------------------
__global__ void __launch_bounds__(256) transpose_split(
    const bf16* __restrict__ Vh, const bf16* __restrict__ Vl,
    bf16* __restrict__ Th, bf16* __restrict__ Tl)
{
    __shared__ float tile[32][33];
    const int b  = blockIdx.z;
    const int h0 = blockIdx.x * 32;
    const int s0 = blockIdx.y * 32;
    const int tx = threadIdx.x & 31;
    const int ty = threadIdx.x >> 5;

    #pragma unroll
    for (int j = 0; j < 4; j++) {
        const int s = s0 + ty + j * 8;
        const long long i = (long long)(b * SEQ + s) * HDIM + h0 + tx;
        tile[ty + j * 8][tx] = __bfloat162float(Vh[i]) + __bfloat162float(Vl[i]);
    }
    __syncthreads();
    #pragma unroll
    for (int j = 0; j < 4; j++) {
        const int h = h0 + ty + j * 8;
        const float v = tile[tx][ty + j * 8];
        bf16 hi, lo; split1(v, hi, lo);
        const long long o = ((long long)b * HDIM + h) * SEQ + s0 + tx;
        Th[o] = hi; Tl[o] = lo;
    }
}

// ---------------------------------------------------------------------------
__global__ void __launch_bounds__(256) softmax_split(
    const float* __restrict__ S, bf16* __restrict__ Ph, bf16* __restrict__ Pl)
{
    __shared__ float buf[SEQ];
    __shared__ float red[8];

    const int tid = threadIdx.x;
    const float2* row2 = reinterpret_cast<const float2*>(S + (long long)blockIdx.x * SEQ);
    float2* b2 = reinterpret_cast<float2*>(buf);

    float m = -1e30f;
    #pragma unroll
    for (int j = 0; j < 4; j++) {
        float2 f = row2[tid + j * 256];
        b2[tid + j * 256] = f;
        m = fmaxf(m, fmaxf(f.x, f.y));
    }
    #pragma unroll
    for (int o = 16; o > 0; o >>= 1)
        m = fmaxf(m, __shfl_xor_sync(0xffffffffu, m, o));
    if ((tid & 31) == 0) red[tid >> 5] = m;
    __syncthreads();
    float bmax = red[0];
    #pragma unroll
    for (int w = 1; w < 8; w++) bmax = fmaxf(bmax, red[w]);
    __syncthreads();

    float s = 0.f;
    #pragma unroll
    for (int j = 0; j < 4; j++) {
        float2 f = b2[tid + j * 256];
        f.x = __expf(f.x - bmax);
        f.y = __expf(f.y - bmax);
        b2[tid + j * 256] = f;
        s += f.x + f.y;
    }
    #pragma unroll
    for (int o = 16; o > 0; o >>= 1)
        s += __shfl_xor_sync(0xffffffffu, s, o);
    if ((tid & 31) == 0) red[tid >> 5] = s;
    __syncthreads();
    float tot = 0.f;
    #pragma unroll
    for (int w = 0; w < 8; w++) tot += red[w];
    const float inv = 1.f / tot;

    __nv_bfloat162* ph2 = reinterpret_cast<__nv_bfloat162*>(Ph) + (long long)blockIdx.x * (SEQ / 2);
    __nv_bfloat162* pl2 = reinterpret_cast<__nv_bfloat162*>(Pl) + (long long)blockIdx.x * (SEQ / 2);
    #pragma unroll
    for (int j = 0; j < 4; j++) {
        float2 f = b2[tid + j * 256];
        const float p0 = f.x * inv, p1 = f.y * inv;
        bf16 h0,l0,h1,l1;
        split1(p0, h0, l0); split1(p1, h1, l1);
        ph2[tid + j * 256] = __halves2bfloat162(h0, h1);
        pl2[tid + j * 256] = __halves2bfloat162(l0, l1);
    }
}

// ---------------------------------------------------------------------------
extern "C" void kernel_launch(void* const* d_in, const int* in_sizes, int n_in,
                              void* d_out, int out_size)
{
    const float* x  = (const float*)d_in[0];
    const float* wq = (const float*)d_in[1];
    const float* bq = (const float*)d_in[2];
    const float* wk = (const float*)d_in[3];
    const float* bk = (const float*)d_in[4];
    const float* wv = (const float*)d_in[5];
    const float* bv = (const float*)d_in[6];
    const float* wo = (const float*)d_in[7];
    const float* bo = (const float*)d_in[8];
    float* out = (float*)d_out;

    static bool attr_done = false;
    if (!attr_done) {
        cudaFuncSetAttribute(bf16s_gemm<0>, cudaFuncAttributeMaxDynamicSharedMemorySize, SMEM_BYTES);
        cudaFuncSetAttribute(bf16s_gemm<1>, cudaFuncAttributeMaxDynamicSharedMemorySize, SMEM_BYTES);
        cudaFuncSetAttribute(bf16s_gemm<2>, cudaFuncAttributeMaxDynamicSharedMemorySize, SMEM_BYTES);
        attr_done = true;
    }

    bf16 *xh,*xl,*wch,*wcl,*woh,*wol;
    bf16 *qh,*ql,*kh,*kl,*vh,*vl,*vth,*vtl,*sh,*sl,*yh,*yl;
    float *s;
    cudaGetSymbolAddress((void**)&xh, g_xh);   cudaGetSymbolAddress((void**)&xl, g_xl);
    cudaGetSymbolAddress((void**)&wch, g_wch); cudaGetSymbolAddress((void**)&wcl, g_wcl);
    cudaGetSymbolAddress((void**)&woh, g_woh); cudaGetSymbolAddress((void**)&wol, g_wol);
    cudaGetSymbolAddress((void**)&qh, g_qh);   cudaGetSymbolAddress((void**)&ql, g_ql);
    cudaGetSymbolAddress((void**)&kh, g_kh);   cudaGetSymbolAddress((void**)&kl, g_kl);
    cudaGetSymbolAddress((void**)&vh, g_vh);   cudaGetSymbolAddress((void**)&vl, g_vl);
    cudaGetSymbolAddress((void**)&vth, g_vth); cudaGetSymbolAddress((void**)&vtl, g_vtl);
    cudaGetSymbolAddress((void**)&s, g_s);
    cudaGetSymbolAddress((void**)&sh, g_sh);   cudaGetSymbolAddress((void**)&sl, g_sl);
    cudaGetSymbolAddress((void**)&yh, g_yh);   cudaGetSymbolAddress((void**)&yl, g_yl);

    const dim3 blk(256);
    const int WSZ = HDIM * NDIM;   // 589824

    // 0) split x and weights (weights concatenated: wq|wk|wv planes)
    split_f32<<<512, blk>>>(x,  xh,  xl,  MTOT * NDIM / 4);
    split_f32<<<128, blk>>>(wq, wch,           wcl,           WSZ / 4);
    split_f32<<<128, blk>>>(wk, wch + WSZ,     wcl + WSZ,     WSZ / 4);
    split_f32<<<128, blk>>>(wv, wch + 2 * WSZ, wcl + 2 * WSZ, WSZ / 4);
    split_f32<<<128, blk>>>(wo, woh, wol, WSZ / 4);

    // 1) fused QKV projection: [8192,768] x [2304,768]^T -> q,k,v split planes
    {
        dim3 grid(3 * HDIM / 128, MTOT / 128, 1);
        bf16s_gemm<2><<<grid, blk, SMEM_BYTES>>>(
            xh, xl, wch, wcl, bq, bk, bv,
            nullptr, qh, ql, kh, kl, vh, vl,
            MTOT, 3 * HDIM, NDIM, HDIM, 0, 0, 0);
    }
    {
        dim3 grid(HDIM / 32, SEQ / 32, BATCH);
        transpose_split<<<grid, blk>>>(vh, vl, vth, vtl);
    }

    // 2) scores = Q K^T (fp32)
    {
        dim3 grid(SEQ / 128, SEQ / 128, BATCH);
        bf16s_gemm<0><<<grid, blk, SMEM_BYTES>>>(
            qh, ql, kh, kl, nullptr, nullptr, nullptr,
            s, nullptr, nullptr, nullptr, nullptr, nullptr, nullptr,
            SEQ, SEQ, HDIM, SEQ,
            (long long)SEQ * HDIM, (long long)SEQ * HDIM, (long long)SEQ * SEQ);
    }

    // 3) softmax -> split bf16 probs
    softmax_split<<<BATCH * SEQ, blk>>>(s, sh, sl);

    // 4) y = P V  (B operand = V^T planes [HDIM, SEQ]) -> split planes
    {
        dim3 grid(HDIM / 128, SEQ / 128, BATCH);
        bf16s_gemm<1><<<grid, blk, SMEM_BYTES>>>(
            sh, sl, vth, vtl, nullptr, nullptr, nullptr,
            nullptr, yh, yl, nullptr, nullptr, nullptr, nullptr,
            SEQ, HDIM, SEQ, HDIM,
            (long long)SEQ * SEQ, (long long)HDIM * SEQ, (long long)SEQ * HDIM);
    }

    // 5) out = Y Wo^T + bo (fp32)
    {
        dim3 grid(NDIM / 128, MTOT / 128, 1);
        bf16s_gemm<0><<<grid, blk, SMEM_BYTES>>>(
            yh, yl, woh, wol, bo, nullptr, nullptr,
            out, nullptr, nullptr, nullptr, nullptr, nullptr, nullptr,
            MTOT, NDIM, HDIM, NDIM, 0, 0, 0);
    }
}

// round 9
// speedup vs baseline: 1.1679x; 1.0047x over previous
#include <cuda_runtime.h>
#include <cuda_bf16.h>
#include <stdint.h>
#include <math.h>

#define BATCH 4
#define SEQ   2048
#define NDIM  768
#define HDIM  768
#define MTOT  (BATCH * SEQ)
#define WSZ   (HDIM * NDIM)

typedef __nv_bfloat16 bf16;

// ------------------------- scratch (allocation-free) ------------------------
__device__ __align__(16) bf16  g_xh[MTOT * NDIM];
__device__ __align__(16) bf16  g_xl[MTOT * NDIM];
__device__ __align__(16) bf16  g_wch[3 * WSZ];   // concat wq|wk|wv planes
__device__ __align__(16) bf16  g_wcl[3 * WSZ];
__device__ __align__(16) bf16  g_woh[WSZ];
__device__ __align__(16) bf16  g_wol[WSZ];
__device__ __align__(16) bf16  g_qh[MTOT * HDIM];
__device__ __align__(16) bf16  g_ql[MTOT * HDIM];
__device__ __align__(16) bf16  g_kh[MTOT * HDIM];
__device__ __align__(16) bf16  g_kl[MTOT * HDIM];
__device__ __align__(16) bf16  g_vh[MTOT * HDIM];
__device__ __align__(16) bf16  g_vl[MTOT * HDIM];
__device__ __align__(16) bf16  g_vth[(long long)BATCH * HDIM * SEQ];
__device__ __align__(16) bf16  g_vtl[(long long)BATCH * HDIM * SEQ];
__device__ __align__(16) float g_s [(long long)BATCH * SEQ * SEQ];
__device__ __align__(16) bf16  g_sh[(long long)BATCH * SEQ * SEQ];
__device__ __align__(16) bf16  g_sl[(long long)BATCH * SEQ * SEQ];
__device__ __align__(16) bf16  g_yh[MTOT * HDIM];
__device__ __align__(16) bf16  g_yl[MTOT * HDIM];
__device__ __align__(16) float g_py[2LL * MTOT * HDIM];   // PV split-K partials
__device__ __align__(16) float g_po[2LL * MTOT * NDIM];   // out-proj partials

// ------------------------------ helpers -------------------------------------
__device__ __forceinline__ void mma16816(float* d, const uint32_t* a, const uint32_t* b)
{
    asm volatile(
        "mma.sync.aligned.m16n8k16.row.col.f32.bf16.bf16.f32 "
        "{%0,%1,%2,%3},{%4,%5,%6,%7},{%8,%9},{%0,%1,%2,%3};\n"
        : "+f"(d[0]), "+f"(d[1]), "+f"(d[2]), "+f"(d[3])
        : "r"(a[0]), "r"(a[1]), "r"(a[2]), "r"(a[3]), "r"(b[0]), "r"(b[1]));
}

__device__ __forceinline__ void ldsm_x4(uint32_t* r, uint32_t addr)
{
    asm volatile("ldmatrix.sync.aligned.m8n8.x4.shared.b16 {%0,%1,%2,%3}, [%4];"
                 : "=r"(r[0]), "=r"(r[1]), "=r"(r[2]), "=r"(r[3]) : "r"(addr));
}

__device__ __forceinline__ void split1(float x, bf16& h, bf16& l)
{
    h = __float2bfloat16(x);
    l = __float2bfloat16(x - __bfloat162float(h));
}

__device__ __forceinline__ void cpa16(uint32_t dst, const void* src)
{
    asm volatile("cp.async.cg.shared.global [%0], [%1], 16;\n" :: "r"(dst), "l"(src));
}
__device__ __forceinline__ void cpa_commit() { asm volatile("cp.async.commit_group;\n"); }
template <int N>
__device__ __forceinline__ void cpa_wait() { asm volatile("cp.async.wait_group %0;\n" :: "n"(N)); }

// smem geometry (uint32 words). Row = 16 data words (32 bf16 of k) + 4 pad.
#define RSTRIDE 20
#define PLANE_W (128 * RSTRIDE)
#define PLANE_B (PLANE_W * 4)
#define STAGE_B (4 * PLANE_B)                // 40960 B
#define SMEM_BYTES (2 * STAGE_B)             // 81920

// ---------------------------------------------------------------------------
// Split-bf16 tensor-core GEMM: C = A * B^T (+bias), generalized with split-K.
// EPI=0: fp32 Cf. EPI=1: split bf16 Ch/Cl. EPI=2: fused-QKV routing.
// grid.z = batches * nsplit; split-k chunk = Kloop, A col offset kOffA etc.
// ---------------------------------------------------------------------------
template <int EPI>
__global__ void __launch_bounds__(256, 2) bf16s_gemm(
    const bf16* __restrict__ Ah, const bf16* __restrict__ Al,
    const bf16* __restrict__ Bh, const bf16* __restrict__ Bl,
    const float* __restrict__ bias0, const float* __restrict__ bias1,
    const float* __restrict__ bias2,
    float* __restrict__ Cf,
    bf16* __restrict__ Ch, bf16* __restrict__ Cl,
    bf16* __restrict__ C2h, bf16* __restrict__ C2l,
    bf16* __restrict__ C3h, bf16* __restrict__ C3l,
    int M, int N, int Kloop, int lda, int ldb, int ldc,
    int nsplit,
    long long sA, long long sB, long long sC,
    long long kOffA, long long kOffB, long long sSplit)
{
    extern __shared__ uint32_t smem[];

    const int bz = blockIdx.z;
    const int batch = bz / nsplit;
    const int split = bz - batch * nsplit;

    Ah += (long long)batch * sA + split * kOffA;
    Al += (long long)batch * sA + split * kOffA;
    Bh += (long long)batch * sB + split * kOffB;
    Bl += (long long)batch * sB + split * kOffB;
    if (EPI == 0) Cf += (long long)batch * sC + split * sSplit;
    else if (EPI == 1) { Ch += (long long)batch * sC; Cl += (long long)batch * sC; }

    const int tid  = threadIdx.x;
    const int lane = tid & 31;
    const int warp = tid >> 5;
    const int bm = blockIdx.y * 128;
    const int bn = blockIdx.x * 128;
    const int wm = (warp & 1) * 64;
    const int wn = (warp >> 1) * 32;
    const int r = lane >> 2;
    const int c = lane & 3;

    // ---- loader mapping: thread -> row=tid/2, two 16B chunks per plane ----
    const int ld_row = tid >> 1;
    const int ld_c0  = (tid & 1) * 2;
    const bf16* pAh = Ah + (long long)(bm + ld_row) * lda + ld_c0 * 8;
    const bf16* pAl = Al + (long long)(bm + ld_row) * lda + ld_c0 * 8;
    const bf16* pBh = Bh + (long long)(bn + ld_row) * ldb + ld_c0 * 8;
    const bf16* pBl = Bl + (long long)(bn + ld_row) * ldb + ld_c0 * 8;

    uint32_t smem_u32;
    asm("{ .reg .u64 t; cvta.to.shared.u64 t, %1; cvt.u32.u64 %0, t; }"
        : "=r"(smem_u32) : "l"(smem));
    const uint32_t dst_base = smem_u32 + (ld_row * RSTRIDE + 4 * ld_c0) * 4;

    auto load_stage = [&](int stage, int k0) {
        const uint32_t d = dst_base + stage * STAGE_B;
        cpa16(d,                pAh + k0);
        cpa16(d + 16,           pAh + k0 + 8);
        cpa16(d + PLANE_B,      pAl + k0);
        cpa16(d + PLANE_B + 16, pAl + k0 + 8);
        cpa16(d + 2 * PLANE_B,      pBh + k0);
        cpa16(d + 2 * PLANE_B + 16, pBh + k0 + 8);
        cpa16(d + 3 * PLANE_B,      pBl + k0);
        cpa16(d + 3 * PLANE_B + 16, pBl + k0 + 8);
    };

    const uint32_t aOff = (((wm + (lane & 15)) * RSTRIDE + ((lane >> 4) << 2)) << 2);
    const uint32_t bOff = (((wn + (lane & 7) + ((lane >> 4) << 3)) * RSTRIDE
                            + (((lane >> 3) & 1) << 2)) << 2);

    float acc[4][4][4];
    #pragma unroll
    for (int i = 0; i < 4; i++)
        #pragma unroll
        for (int j = 0; j < 4; j++)
            #pragma unroll
            for (int e = 0; e < 4; e++) acc[i][j][e] = 0.f;

    const int T = Kloop / 32;

    load_stage(0, 0);  cpa_commit();
    if (T > 1) load_stage(1, 32);
    cpa_commit();

    for (int t = 0; t < T; t++) {
        cpa_wait<1>();
        __syncthreads();

        const uint32_t stage_base = smem_u32 + (t & 1) * STAGE_B;
        const uint32_t aBaseH = stage_base + aOff;
        const uint32_t aBaseL = aBaseH + PLANE_B;
        const uint32_t bBaseH = stage_base + 2 * PLANE_B + bOff;
        const uint32_t bBaseL = bBaseH + PLANE_B;

        #pragma unroll
        for (int ks = 0; ks < 2; ks++) {
            const uint32_t kb = ks * 32;
            uint32_t aH[4][4], aL[4][4], bH[4][2], bL[4][2];
            #pragma unroll
            for (int mi = 0; mi < 4; mi++) {
                ldsm_x4(aH[mi], aBaseH + mi * (16 * RSTRIDE * 4) + kb);
                ldsm_x4(aL[mi], aBaseL + mi * (16 * RSTRIDE * 4) + kb);
            }
            #pragma unroll
            for (int np = 0; np < 2; np++) {
                uint32_t th[4], tl[4];
                ldsm_x4(th, bBaseH + np * (16 * RSTRIDE * 4) + kb);
                ldsm_x4(tl, bBaseL + np * (16 * RSTRIDE * 4) + kb);
                bH[2*np][0] = th[0]; bH[2*np][1] = th[1];
                bH[2*np+1][0] = th[2]; bH[2*np+1][1] = th[3];
                bL[2*np][0] = tl[0]; bL[2*np][1] = tl[1];
                bL[2*np+1][0] = tl[2]; bL[2*np+1][1] = tl[3];
            }
            #pragma unroll
            for (int mi = 0; mi < 4; mi++)
                #pragma unroll
                for (int ni = 0; ni < 4; ni++) {
                    mma16816(acc[mi][ni], aH[mi], bH[ni]);
                    mma16816(acc[mi][ni], aH[mi], bL[ni]);
                    mma16816(acc[mi][ni], aL[mi], bH[ni]);
                }
        }
        __syncthreads();

        if (t + 2 < T) load_stage(t & 1, (t + 2) * 32);
        cpa_commit();
    }

    // ---------------- epilogue ----------------
    const float* bias = bias0;
    bf16* dh = Ch; bf16* dl = Cl;
    int cb = bn;
    int stride = ldc;
    if (EPI == 2) {
        const int seg = bn / 768;
        cb = bn - seg * 768;
        stride = 768;
        if (seg == 1) { bias = bias1; dh = C2h; dl = C2l; }
        else if (seg == 2) { bias = bias2; dh = C3h; dl = C3l; }
    }

    #pragma unroll
    for (int mi = 0; mi < 4; mi++)
        #pragma unroll
        for (int ni = 0; ni < 4; ni++) {
            const int row = bm + wm + mi * 16 + r;
            const int col = cb + wn + ni * 8 + 2 * c;
            float v00 = acc[mi][ni][0], v01 = acc[mi][ni][1];
            float v10 = acc[mi][ni][2], v11 = acc[mi][ni][3];
            if (EPI != 0 && bias) {
                const float b0 = bias[col], b1 = bias[col + 1];
                v00 += b0; v01 += b1; v10 += b0; v11 += b1;
            }
            if (EPI == 0) {
                *reinterpret_cast<float2*>(Cf + (long long)row * stride + col)
                    = make_float2(v00, v01);
                *reinterpret_cast<float2*>(Cf + (long long)(row + 8) * stride + col)
                    = make_float2(v10, v11);
            } else {
                bf16 h0, l0, h1, l1;
                split1(v00, h0, l0); split1(v01, h1, l1);
                *reinterpret_cast<__nv_bfloat162*>(dh + (long long)row * stride + col)
                    = __halves2bfloat162(h0, h1);
                *reinterpret_cast<__nv_bfloat162*>(dl + (long long)row * stride + col)
                    = __halves2bfloat162(l0, l1);
                split1(v10, h0, l0); split1(v11, h1, l1);
                *reinterpret_cast<__nv_bfloat162*>(dh + (long long)(row + 8) * stride + col)
                    = __halves2bfloat162(h0, h1);
                *reinterpret_cast<__nv_bfloat162*>(dl + (long long)(row + 8) * stride + col)
                    = __halves2bfloat162(l0, l1);
            }
        }
}

// ---------------------------------------------------------------------------
// All input splits in ONE launch. grid.y selects the segment.
// ---------------------------------------------------------------------------
__global__ void __launch_bounds__(256) split_all(
    const float* __restrict__ x,  const float* __restrict__ wq,
    const float* __restrict__ wk, const float* __restrict__ wv,
    const float* __restrict__ wo,
    bf16* __restrict__ xh, bf16* __restrict__ xl,
    bf16* __restrict__ wch, bf16* __restrict__ wcl,
    bf16* __restrict__ woh, bf16* __restrict__ wol)
{
    const float* in; bf16 *h, *l; int n4;
    switch (blockIdx.y) {
        case 0: in = x;  h = xh;            l = xl;            n4 = MTOT * NDIM / 4; break;
        case 1: in = wq; h = wch;           l = wcl;           n4 = WSZ / 4; break;
        case 2: in = wk; h = wch + WSZ;     l = wcl + WSZ;     n4 = WSZ / 4; break;
        case 3: in = wv; h = wch + 2 * WSZ; l = wcl + 2 * WSZ; n4 = WSZ / 4; break;
        default:in = wo; h = woh;           l = wol;           n4 = WSZ / 4; break;
    }
    for (int i = blockIdx.x * blockDim.x + threadIdx.x; i < n4;
         i += gridDim.x * blockDim.x) {
        float4 v = reinterpret_cast<const float4*>(in)[i];
        bf16 h0,l0,h1,l1,h2,l2,h3,l3;
        split1(v.x, h0, l0); split1(v.y, h1, l1);
        split1(v.z, h2, l2); split1(v.w, h3, l3);
        reinterpret_cast<__nv_bfloat162*>(h)[2 * i]     = __halves2bfloat162(h0, h1);
        reinterpret_cast<__nv_bfloat162*>(h)[2 * i + 1] = __halves2bfloat162(h2, h3);
        reinterpret_cast<__nv_bfloat162*>(l)[2 * i]     = __halves2bfloat162(l0, l1);
        reinterpret_cast<__nv_bfloat162*>(l)[2 * i + 1] = __halves2bfloat162(l2, l3);
    }
}

// ---------------------------------------------------------------------------
// combine split-K partials -> split bf16 planes (for y)
// ---------------------------------------------------------------------------
__global__ void __launch_bounds__(256) combine_split(
    const float* __restrict__ p0, const float* __restrict__ p1,
    bf16* __restrict__ h, bf16* __restrict__ l, int n4)
{
    for (int i = blockIdx.x * blockDim.x + threadIdx.x; i < n4;
         i += gridDim.x * blockDim.x) {
        float4 a = reinterpret_cast<const float4*>(p0)[i];
        float4 b = reinterpret_cast<const float4*>(p1)[i];
        a.x += b.x; a.y += b.y; a.z += b.z; a.w += b.w;
        bf16 h0,l0,h1,l1,h2,l2,h3,l3;
        split1(a.x, h0, l0); split1(a.y, h1, l1);
        split1(a.z, h2, l2); split1(a.w, h3, l3);
        reinterpret_cast<__nv_bfloat162*>(h)[2 * i]     = __halves2bfloat162(h0, h1);
        reinterpret_cast<__nv_bfloat162*>(h)[2 * i + 1] = __halves2bfloat162(h2, h3);
        reinterpret_cast<__nv_bfloat162*>(l)[2 * i]     = __halves2bfloat162(l0, l1);
        reinterpret_cast<__nv_bfloat162*>(l)[2 * i + 1] = __halves2bfloat162(l2, l3);
    }
}

// ---------------------------------------------------------------------------
// combine split-K partials + bias -> fp32 out (for final projection)
// ---------------------------------------------------------------------------
__global__ void __launch_bounds__(256) combine_bias(
    const float* __restrict__ p0, const float* __restrict__ p1,
    const float* __restrict__ bias, float* __restrict__ out, int n4)
{
    for (int i = blockIdx.x * blockDim.x + threadIdx.x; i < n4;
         i += gridDim.x * blockDim.x) {
        float4 a = reinterpret_cast<const float4*>(p0)[i];
        float4 b = reinterpret_cast<const float4*>(p1)[i];
        float4 bb = reinterpret_cast<const float4*>(bias)[i % (NDIM / 4)];
        a.x += b.x + bb.x; a.y += b.y + bb.y;
        a.z += b.z + bb.z; a.w += b.w + bb.w;
        reinterpret_cast<float4*>(out)[i] = a;
    }
}

// ---------------------------------------------------------------------------
__global__ void __launch_bounds__(256) transpose_split(
    const bf16* __restrict__ Vh, const bf16* __restrict__ Vl,
    bf16* __restrict__ Th, bf16* __restrict__ Tl)
{
    __shared__ float tile[32][33];
    const int b  = blockIdx.z;
    const int h0 = blockIdx.x * 32;
    const int s0 = blockIdx.y * 32;
    const int tx = threadIdx.x & 31;
    const int ty = threadIdx.x >> 5;

    #pragma unroll
    for (int j = 0; j < 4; j++) {
        const int s = s0 + ty + j * 8;
        const long long i = (long long)(b * SEQ + s) * HDIM + h0 + tx;
        tile[ty + j * 8][tx] = __bfloat162float(Vh[i]) + __bfloat162float(Vl[i]);
    }
    __syncthreads();
    #pragma unroll
    for (int j = 0; j < 4; j++) {
        const int h = h0 + ty + j * 8;
        const float v = tile[tx][ty + j * 8];
        bf16 hi, lo; split1(v, hi, lo);
        const long long o = ((long long)b * HDIM + h) * SEQ + s0 + tx;
        Th[o] = hi; Tl[o] = lo;
    }
}

// ---------------------------------------------------------------------------
__global__ void __launch_bounds__(256) softmax_split(
    const float* __restrict__ S, bf16* __restrict__ Ph, bf16* __restrict__ Pl)
{
    __shared__ float buf[SEQ];
    __shared__ float red[8];

    const int tid = threadIdx.x;
    const float2* row2 = reinterpret_cast<const float2*>(S + (long long)blockIdx.x * SEQ);
    float2* b2 = reinterpret_cast<float2*>(buf);

    float m = -1e30f;
    #pragma unroll
    for (int j = 0; j < 4; j++) {
        float2 f = row2[tid + j * 256];
        b2[tid + j * 256] = f;
        m = fmaxf(m, fmaxf(f.x, f.y));
    }
    #pragma unroll
    for (int o = 16; o > 0; o >>= 1)
        m = fmaxf(m, __shfl_xor_sync(0xffffffffu, m, o));
    if ((tid & 31) == 0) red[tid >> 5] = m;
    __syncthreads();
    float bmax = red[0];
    #pragma unroll
    for (int w = 1; w < 8; w++) bmax = fmaxf(bmax, red[w]);
    __syncthreads();

    float s = 0.f;
    #pragma unroll
    for (int j = 0; j < 4; j++) {
        float2 f = b2[tid + j * 256];
        f.x = __expf(f.x - bmax);
        f.y = __expf(f.y - bmax);
        b2[tid + j * 256] = f;
        s += f.x + f.y;
    }
    #pragma unroll
    for (int o = 16; o > 0; o >>= 1)
        s += __shfl_xor_sync(0xffffffffu, s, o);
    if ((tid & 31) == 0) red[tid >> 5] = s;
    __syncthreads();
    float tot = 0.f;
    #pragma unroll
    for (int w = 0; w < 8; w++) tot += red[w];
    const float inv = 1.f / tot;

    __nv_bfloat162* ph2 = reinterpret_cast<__nv_bfloat162*>(Ph) + (long long)blockIdx.x * (SEQ / 2);
    __nv_bfloat162* pl2 = reinterpret_cast<__nv_bfloat162*>(Pl) + (long long)blockIdx.x * (SEQ / 2);
    #pragma unroll
    for (int j = 0; j < 4; j++) {
        float2 f = b2[tid + j * 256];
        const float p0 = f.x * inv, p1 = f.y * inv;
        bf16 h0,l0,h1,l1;
        split1(p0, h0, l0); split1(p1, h1, l1);
        ph2[tid + j * 256] = __halves2bfloat162(h0, h1);
        pl2[tid + j * 256] = __halves2bfloat162(l0, l1);
    }
}

// ---------------------------------------------------------------------------
extern "C" void kernel_launch(void* const* d_in, const int* in_sizes, int n_in,
                              void* d_out, int out_size)
{
    const float* x  = (const float*)d_in[0];
    const float* wq = (const float*)d_in[1];
    const float* bq = (const float*)d_in[2];
    const float* wk = (const float*)d_in[3];
    const float* bk = (const float*)d_in[4];
    const float* wv = (const float*)d_in[5];
    const float* bv = (const float*)d_in[6];
    const float* wo = (const float*)d_in[7];
    const float* bo = (const float*)d_in[8];
    float* out = (float*)d_out;

    static bool attr_done = false;
    if (!attr_done) {
        cudaFuncSetAttribute(bf16s_gemm<0>, cudaFuncAttributeMaxDynamicSharedMemorySize, SMEM_BYTES);
        cudaFuncSetAttribute(bf16s_gemm<1>, cudaFuncAttributeMaxDynamicSharedMemorySize, SMEM_BYTES);
        cudaFuncSetAttribute(bf16s_gemm<2>, cudaFuncAttributeMaxDynamicSharedMemorySize, SMEM_BYTES);
        attr_done = true;
    }

    bf16 *xh,*xl,*wch,*wcl,*woh,*wol;
    bf16 *qh,*ql,*kh,*kl,*vh,*vl,*vth,*vtl,*sh,*sl,*yh,*yl;
    float *s, *py, *po;
    cudaGetSymbolAddress((void**)&xh, g_xh);   cudaGetSymbolAddress((void**)&xl, g_xl);
    cudaGetSymbolAddress((void**)&wch, g_wch); cudaGetSymbolAddress((void**)&wcl, g_wcl);
    cudaGetSymbolAddress((void**)&woh, g_woh); cudaGetSymbolAddress((void**)&wol, g_wol);
    cudaGetSymbolAddress((void**)&qh, g_qh);   cudaGetSymbolAddress((void**)&ql, g_ql);
    cudaGetSymbolAddress((void**)&kh, g_kh);   cudaGetSymbolAddress((void**)&kl, g_kl);
    cudaGetSymbolAddress((void**)&vh, g_vh);   cudaGetSymbolAddress((void**)&vl, g_vl);
    cudaGetSymbolAddress((void**)&vth, g_vth); cudaGetSymbolAddress((void**)&vtl, g_vtl);
    cudaGetSymbolAddress((void**)&s, g_s);
    cudaGetSymbolAddress((void**)&sh, g_sh);   cudaGetSymbolAddress((void**)&sl, g_sl);
    cudaGetSymbolAddress((void**)&yh, g_yh);   cudaGetSymbolAddress((void**)&yl, g_yl);
    cudaGetSymbolAddress((void**)&py, g_py);
    cudaGetSymbolAddress((void**)&po, g_po);

    const dim3 blk(256);

    // 0) all splits in one launch
    {
        dim3 grid(512, 5, 1);
        split_all<<<grid, blk>>>(x, wq, wk, wv, wo, xh, xl, wch, wcl, woh, wol);
    }

    // 1) fused QKV projection: [8192,768] x [2304,768]^T -> q,k,v split planes
    {
        dim3 grid(3 * HDIM / 128, MTOT / 128, 1);
        bf16s_gemm<2><<<grid, blk, SMEM_BYTES>>>(
            xh, xl, wch, wcl, bq, bk, bv,
            nullptr, qh, ql, kh, kl, vh, vl,
            MTOT, 3 * HDIM, NDIM, NDIM, NDIM, HDIM, 1, 0, 0, 0, 0, 0, 0);
    }
    {
        dim3 grid(HDIM / 32, SEQ / 32, BATCH);
        transpose_split<<<grid, blk>>>(vh, vl, vth, vtl);
    }

    // 2) scores = Q K^T (fp32)
    {
        dim3 grid(SEQ / 128, SEQ / 128, BATCH);
        bf16s_gemm<0><<<grid, blk, SMEM_BYTES>>>(
            qh, ql, kh, kl, nullptr, nullptr, nullptr,
            s, nullptr, nullptr, nullptr, nullptr, nullptr, nullptr,
            SEQ, SEQ, HDIM, HDIM, HDIM, SEQ, 1,
            (long long)SEQ * HDIM, (long long)SEQ * HDIM, (long long)SEQ * SEQ,
            0, 0, 0);
    }

    // 3) softmax -> split bf16 probs
    softmax_split<<<BATCH * SEQ, blk>>>(s, sh, sl);

    // 4) y = P V  (split-K=2): partials into py[split][batch][seq][hdim]
    {
        dim3 grid(HDIM / 128, SEQ / 128, BATCH * 2);
        bf16s_gemm<0><<<grid, blk, SMEM_BYTES>>>(
            sh, sl, vth, vtl, nullptr, nullptr, nullptr,
            py, nullptr, nullptr, nullptr, nullptr, nullptr, nullptr,
            SEQ, HDIM, SEQ / 2, SEQ, SEQ, HDIM, 2,
            (long long)SEQ * SEQ, (long long)HDIM * SEQ, (long long)SEQ * HDIM,
            SEQ / 2, SEQ / 2, (long long)MTOT * HDIM);
    }
    combine_split<<<512, blk>>>(py, py + (long long)MTOT * HDIM, yh, yl, MTOT * HDIM / 4);

    // 5) out = Y Wo^T + bo (split-K=2)
    {
        dim3 grid(NDIM / 128, MTOT / 128, 2);
        bf16s_gemm<0><<<grid, blk, SMEM_BYTES>>>(
            yh, yl, woh, wol, nullptr, nullptr, nullptr,
            po, nullptr, nullptr, nullptr, nullptr, nullptr, nullptr,
            MTOT, NDIM, HDIM / 2, HDIM, HDIM, NDIM, 2,
            0, 0, 0,
            HDIM / 2, HDIM / 2, (long long)MTOT * NDIM);
    }
    combine_bias<<<512, blk>>>(po, po + (long long)MTOT * NDIM, bo, out, MTOT * NDIM / 4);
}

// round 10
// speedup vs baseline: 1.2661x; 1.0841x over previous
#include <cuda_runtime.h>
#include <cuda_fp16.h>
#include <stdint.h>
#include <math.h>

#define BATCH 4
#define SEQ   2048
#define NDIM  768
#define HDIM  768
#define MTOT  (BATCH * SEQ)
#define WSZ   (HDIM * NDIM)

typedef __half hf;

// ------------------------- scratch (allocation-free) ------------------------
__device__ __align__(16) hf    g_xh[MTOT * NDIM];
__device__ __align__(16) hf    g_xl[MTOT * NDIM];
__device__ __align__(16) hf    g_wch[3 * WSZ];   // concat wq|wk|wv planes
__device__ __align__(16) hf    g_wcl[3 * WSZ];
__device__ __align__(16) hf    g_woh[WSZ];
__device__ __align__(16) hf    g_wol[WSZ];
__device__ __align__(16) hf    g_qh[MTOT * HDIM];
__device__ __align__(16) hf    g_ql[MTOT * HDIM];
__device__ __align__(16) hf    g_kh[MTOT * HDIM];
__device__ __align__(16) hf    g_kl[MTOT * HDIM];
__device__ __align__(16) hf    g_vh[MTOT * HDIM];
__device__ __align__(16) hf    g_vl[MTOT * HDIM];
__device__ __align__(16) hf    g_vth[(long long)BATCH * HDIM * SEQ];
__device__ __align__(16) hf    g_vtl[(long long)BATCH * HDIM * SEQ];
__device__ __align__(16) float g_s [(long long)BATCH * SEQ * SEQ];
__device__ __align__(16) hf    g_sh[(long long)BATCH * SEQ * SEQ];
__device__ __align__(16) hf    g_yh[MTOT * HDIM];
__device__ __align__(16) hf    g_yl[MTOT * HDIM];
__device__ __align__(16) float g_py[2LL * MTOT * HDIM];   // PV split-K partials
__device__ __align__(16) float g_po[2LL * MTOT * NDIM];   // out-proj partials

// ------------------------------ helpers -------------------------------------
__device__ __forceinline__ void mma16816(float* d, const uint32_t* a, const uint32_t* b)
{
    asm volatile(
        "mma.sync.aligned.m16n8k16.row.col.f32.f16.f16.f32 "
        "{%0,%1,%2,%3},{%4,%5,%6,%7},{%8,%9},{%0,%1,%2,%3};\n"
        : "+f"(d[0]), "+f"(d[1]), "+f"(d[2]), "+f"(d[3])
        : "r"(a[0]), "r"(a[1]), "r"(a[2]), "r"(a[3]), "r"(b[0]), "r"(b[1]));
}

__device__ __forceinline__ void ldsm_x4(uint32_t* r, uint32_t addr)
{
    asm volatile("ldmatrix.sync.aligned.m8n8.x4.shared.b16 {%0,%1,%2,%3}, [%4];"
                 : "=r"(r[0]), "=r"(r[1]), "=r"(r[2]), "=r"(r[3]) : "r"(addr));
}

__device__ __forceinline__ void split1(float x, hf& h, hf& l)
{
    h = __float2half(x);
    l = __float2half(x - __half2float(h));
}

__device__ __forceinline__ void cpa16(uint32_t dst, const void* src)
{
    asm volatile("cp.async.cg.shared.global [%0], [%1], 16;\n" :: "r"(dst), "l"(src));
}
__device__ __forceinline__ void cpa_commit() { asm volatile("cp.async.commit_group;\n"); }
template <int N>
__device__ __forceinline__ void cpa_wait() { asm volatile("cp.async.wait_group %0;\n" :: "n"(N)); }

// smem geometry (uint32 words). Row = 16 data words (32 halves of k) + 4 pad.
#define RSTRIDE 20
#define PLANE_W (128 * RSTRIDE)
#define PLANE_B (PLANE_W * 4)
#define STAGE_B (4 * PLANE_B)                // 40960 B
#define SMEM_BYTES (2 * STAGE_B)             // 81920

// ---------------------------------------------------------------------------
// Split-fp16 tensor-core GEMM: C = A * B^T (+bias), split-K capable.
// EPI=0: fp32 Cf. EPI=2: fused-QKV routing to 3 split-plane dests.
// NT=3: hh + hl + lh.   NT=2: hh + hl (A-lo plane unused & not loaded).
// ---------------------------------------------------------------------------
template <int EPI, int NT>
__global__ void __launch_bounds__(256, 2) hfs_gemm(
    const hf* __restrict__ Ah, const hf* __restrict__ Al,
    const hf* __restrict__ Bh, const hf* __restrict__ Bl,
    const float* __restrict__ bias0, const float* __restrict__ bias1,
    const float* __restrict__ bias2,
    float* __restrict__ Cf,
    hf* __restrict__ Ch, hf* __restrict__ Cl,
    hf* __restrict__ C2h, hf* __restrict__ C2l,
    hf* __restrict__ C3h, hf* __restrict__ C3l,
    int M, int N, int Kloop, int lda, int ldb, int ldc,
    int nsplit,
    long long sA, long long sB, long long sC,
    long long kOffA, long long kOffB, long long sSplit)
{
    extern __shared__ uint32_t smem[];

    const int bz = blockIdx.z;
    const int batch = bz / nsplit;
    const int split = bz - batch * nsplit;

    Ah += (long long)batch * sA + split * kOffA;
    Al += (long long)batch * sA + split * kOffA;
    Bh += (long long)batch * sB + split * kOffB;
    Bl += (long long)batch * sB + split * kOffB;
    if (EPI == 0) Cf += (long long)batch * sC + split * sSplit;

    const int tid  = threadIdx.x;
    const int lane = tid & 31;
    const int warp = tid >> 5;
    const int bm = blockIdx.y * 128;
    const int bn = blockIdx.x * 128;
    const int wm = (warp & 1) * 64;
    const int wn = (warp >> 1) * 32;
    const int r = lane >> 2;
    const int c = lane & 3;

    // ---- loader mapping: thread -> row=tid/2, two 16B chunks per plane ----
    const int ld_row = tid >> 1;
    const int ld_c0  = (tid & 1) * 2;
    const hf* pAh = Ah + (long long)(bm + ld_row) * lda + ld_c0 * 8;
    const hf* pAl = Al + (long long)(bm + ld_row) * lda + ld_c0 * 8;
    const hf* pBh = Bh + (long long)(bn + ld_row) * ldb + ld_c0 * 8;
    const hf* pBl = Bl + (long long)(bn + ld_row) * ldb + ld_c0 * 8;

    uint32_t smem_u32;
    asm("{ .reg .u64 t; cvta.to.shared.u64 t, %1; cvt.u32.u64 %0, t; }"
        : "=r"(smem_u32) : "l"(smem));
    const uint32_t dst_base = smem_u32 + (ld_row * RSTRIDE + 4 * ld_c0) * 4;

    auto load_stage = [&](int stage, int k0) {
        const uint32_t d = dst_base + stage * STAGE_B;
        cpa16(d,                pAh + k0);
        cpa16(d + 16,           pAh + k0 + 8);
        if (NT == 3) {
            cpa16(d + PLANE_B,      pAl + k0);
            cpa16(d + PLANE_B + 16, pAl + k0 + 8);
        }
        cpa16(d + 2 * PLANE_B,      pBh + k0);
        cpa16(d + 2 * PLANE_B + 16, pBh + k0 + 8);
        cpa16(d + 3 * PLANE_B,      pBl + k0);
        cpa16(d + 3 * PLANE_B + 16, pBl + k0 + 8);
    };

    const uint32_t aOff = (((wm + (lane & 15)) * RSTRIDE + ((lane >> 4) << 2)) << 2);
    const uint32_t bOff = (((wn + (lane & 7) + ((lane >> 4) << 3)) * RSTRIDE
                            + (((lane >> 3) & 1) << 2)) << 2);

    float acc[4][4][4];
    #pragma unroll
    for (int i = 0; i < 4; i++)
        #pragma unroll
        for (int j = 0; j < 4; j++)
            #pragma unroll
            for (int e = 0; e < 4; e++) acc[i][j][e] = 0.f;

    const int T = Kloop / 32;

    load_stage(0, 0);  cpa_commit();
    if (T > 1) load_stage(1, 32);
    cpa_commit();

    for (int t = 0; t < T; t++) {
        cpa_wait<1>();
        __syncthreads();

        const uint32_t stage_base = smem_u32 + (t & 1) * STAGE_B;
        const uint32_t aBaseH = stage_base + aOff;
        const uint32_t aBaseL = aBaseH + PLANE_B;
        const uint32_t bBaseH = stage_base + 2 * PLANE_B + bOff;
        const uint32_t bBaseL = bBaseH + PLANE_B;

        #pragma unroll
        for (int ks = 0; ks < 2; ks++) {
            const uint32_t kb = ks * 32;
            uint32_t aH[4][4], aL[4][4], bH[4][2], bL[4][2];
            #pragma unroll
            for (int mi = 0; mi < 4; mi++) {
                ldsm_x4(aH[mi], aBaseH + mi * (16 * RSTRIDE * 4) + kb);
                if (NT == 3)
                    ldsm_x4(aL[mi], aBaseL + mi * (16 * RSTRIDE * 4) + kb);
            }
            #pragma unroll
            for (int np = 0; np < 2; np++) {
                uint32_t th[4], tl[4];
                ldsm_x4(th, bBaseH + np * (16 * RSTRIDE * 4) + kb);
                ldsm_x4(tl, bBaseL + np * (16 * RSTRIDE * 4) + kb);
                bH[2*np][0] = th[0]; bH[2*np][1] = th[1];
                bH[2*np+1][0] = th[2]; bH[2*np+1][1] = th[3];
                bL[2*np][0] = tl[0]; bL[2*np][1] = tl[1];
                bL[2*np+1][0] = tl[2]; bL[2*np+1][1] = tl[3];
            }
            #pragma unroll
            for (int mi = 0; mi < 4; mi++)
                #pragma unroll
                for (int ni = 0; ni < 4; ni++) {
                    mma16816(acc[mi][ni], aH[mi], bH[ni]);
                    mma16816(acc[mi][ni], aH[mi], bL[ni]);
                    if (NT == 3)
                        mma16816(acc[mi][ni], aL[mi], bH[ni]);
                }
        }
        __syncthreads();

        if (t + 2 < T) load_stage(t & 1, (t + 2) * 32);
        cpa_commit();
    }

    // ---------------- epilogue ----------------
    const float* bias = bias0;
    hf* dh = Ch; hf* dl = Cl;
    int cb = bn;
    int stride = ldc;
    if (EPI == 2) {
        const int seg = bn / 768;
        cb = bn - seg * 768;
        stride = 768;
        if (seg == 1) { bias = bias1; dh = C2h; dl = C2l; }
        else if (seg == 2) { bias = bias2; dh = C3h; dl = C3l; }
    }

    #pragma unroll
    for (int mi = 0; mi < 4; mi++)
        #pragma unroll
        for (int ni = 0; ni < 4; ni++) {
            const int row = bm + wm + mi * 16 + r;
            const int col = cb + wn + ni * 8 + 2 * c;
            float v00 = acc[mi][ni][0], v01 = acc[mi][ni][1];
            float v10 = acc[mi][ni][2], v11 = acc[mi][ni][3];
            if (EPI != 0 && bias) {
                const float b0 = bias[col], b1 = bias[col + 1];
                v00 += b0; v01 += b1; v10 += b0; v11 += b1;
            }
            if (EPI == 0) {
                *reinterpret_cast<float2*>(Cf + (long long)row * stride + col)
                    = make_float2(v00, v01);
                *reinterpret_cast<float2*>(Cf + (long long)(row + 8) * stride + col)
                    = make_float2(v10, v11);
            } else {
                hf h0, l0, h1, l1;
                split1(v00, h0, l0); split1(v01, h1, l1);
                *reinterpret_cast<__half2*>(dh + (long long)row * stride + col)
                    = __halves2half2(h0, h1);
                *reinterpret_cast<__half2*>(dl + (long long)row * stride + col)
                    = __halves2half2(l0, l1);
                split1(v10, h0, l0); split1(v11, h1, l1);
                *reinterpret_cast<__half2*>(dh + (long long)(row + 8) * stride + col)
                    = __halves2half2(h0, h1);
                *reinterpret_cast<__half2*>(dl + (long long)(row + 8) * stride + col)
                    = __halves2half2(l0, l1);
            }
        }
}

// ---------------------------------------------------------------------------
// All input splits in ONE launch. grid.y selects the segment.
// ---------------------------------------------------------------------------
__global__ void __launch_bounds__(256) split_all(
    const float* __restrict__ x,  const float* __restrict__ wq,
    const float* __restrict__ wk, const float* __restrict__ wv,
    const float* __restrict__ wo,
    hf* __restrict__ xh, hf* __restrict__ xl,
    hf* __restrict__ wch, hf* __restrict__ wcl,
    hf* __restrict__ woh, hf* __restrict__ wol)
{
    const float* in; hf *h, *l; int n4;
    switch (blockIdx.y) {
        case 0: in = x;  h = xh;            l = xl;            n4 = MTOT * NDIM / 4; break;
        case 1: in = wq; h = wch;           l = wcl;           n4 = WSZ / 4; break;
        case 2: in = wk; h = wch + WSZ;     l = wcl + WSZ;     n4 = WSZ / 4; break;
        case 3: in = wv; h = wch + 2 * WSZ; l = wcl + 2 * WSZ; n4 = WSZ / 4; break;
        default:in = wo; h = woh;           l = wol;           n4 = WSZ / 4; break;
    }
    for (int i = blockIdx.x * blockDim.x + threadIdx.x; i < n4;
         i += gridDim.x * blockDim.x) {
        float4 v = reinterpret_cast<const float4*>(in)[i];
        hf h0,l0,h1,l1,h2,l2,h3,l3;
        split1(v.x, h0, l0); split1(v.y, h1, l1);
        split1(v.z, h2, l2); split1(v.w, h3, l3);
        reinterpret_cast<__half2*>(h)[2 * i]     = __halves2half2(h0, h1);
        reinterpret_cast<__half2*>(h)[2 * i + 1] = __halves2half2(h2, h3);
        reinterpret_cast<__half2*>(l)[2 * i]     = __halves2half2(l0, l1);
        reinterpret_cast<__half2*>(l)[2 * i + 1] = __halves2half2(l2, l3);
    }
}

// ---------------------------------------------------------------------------
__global__ void __launch_bounds__(256) combine_split(
    const float* __restrict__ p0, const float* __restrict__ p1,
    hf* __restrict__ h, hf* __restrict__ l, int n4)
{
    for (int i = blockIdx.x * blockDim.x + threadIdx.x; i < n4;
         i += gridDim.x * blockDim.x) {
        float4 a = reinterpret_cast<const float4*>(p0)[i];
        float4 b = reinterpret_cast<const float4*>(p1)[i];
        a.x += b.x; a.y += b.y; a.z += b.z; a.w += b.w;
        hf h0,l0,h1,l1,h2,l2,h3,l3;
        split1(a.x, h0, l0); split1(a.y, h1, l1);
        split1(a.z, h2, l2); split1(a.w, h3, l3);
        reinterpret_cast<__half2*>(h)[2 * i]     = __halves2half2(h0, h1);
        reinterpret_cast<__half2*>(h)[2 * i + 1] = __halves2half2(h2, h3);
        reinterpret_cast<__half2*>(l)[2 * i]     = __halves2half2(l0, l1);
        reinterpret_cast<__half2*>(l)[2 * i + 1] = __halves2half2(l2, l3);
    }
}

// ---------------------------------------------------------------------------
__global__ void __launch_bounds__(256) combine_bias(
    const float* __restrict__ p0, const float* __restrict__ p1,
    const float* __restrict__ bias, float* __restrict__ out, int n4)
{
    for (int i = blockIdx.x * blockDim.x + threadIdx.x; i < n4;
         i += gridDim.x * blockDim.x) {
        float4 a = reinterpret_cast<const float4*>(p0)[i];
        float4 b = reinterpret_cast<const float4*>(p1)[i];
        float4 bb = reinterpret_cast<const float4*>(bias)[i % (NDIM / 4)];
        a.x += b.x + bb.x; a.y += b.y + bb.y;
        a.z += b.z + bb.z; a.w += b.w + bb.w;
        reinterpret_cast<float4*>(out)[i] = a;
    }
}

// ---------------------------------------------------------------------------
__global__ void __launch_bounds__(256) transpose_split(
    const hf* __restrict__ Vh, const hf* __restrict__ Vl,
    hf* __restrict__ Th, hf* __restrict__ Tl)
{
    __shared__ float tile[32][33];
    const int b  = blockIdx.z;
    const int h0 = blockIdx.x * 32;
    const int s0 = blockIdx.y * 32;
    const int tx = threadIdx.x & 31;
    const int ty = threadIdx.x >> 5;

    #pragma unroll
    for (int j = 0; j < 4; j++) {
        const int s = s0 + ty + j * 8;
        const long long i = (long long)(b * SEQ + s) * HDIM + h0 + tx;
        tile[ty + j * 8][tx] = __half2float(Vh[i]) + __half2float(Vl[i]);
    }
    __syncthreads();
    #pragma unroll
    for (int j = 0; j < 4; j++) {
        const int h = h0 + ty + j * 8;
        const float v = tile[tx][ty + j * 8];
        hf hi, lo; split1(v, hi, lo);
        const long long o = ((long long)b * HDIM + h) * SEQ + s0 + tx;
        Th[o] = hi; Tl[o] = lo;
    }
}

// ---------------------------------------------------------------------------
// Row softmax: fp32 scores -> fp16 probs (hi plane only; PV uses 2-term)
// ---------------------------------------------------------------------------
__global__ void __launch_bounds__(256) softmax_h(
    const float* __restrict__ S, hf* __restrict__ Ph)
{
    __shared__ float buf[SEQ];
    __shared__ float red[8];

    const int tid = threadIdx.x;
    const float2* row2 = reinterpret_cast<const float2*>(S + (long long)blockIdx.x * SEQ);
    float2* b2 = reinterpret_cast<float2*>(buf);

    float m = -1e30f;
    #pragma unroll
    for (int j = 0; j < 4; j++) {
        float2 f = row2[tid + j * 256];
        b2[tid + j * 256] = f;
        m = fmaxf(m, fmaxf(f.x, f.y));
    }
    #pragma unroll
    for (int o = 16; o > 0; o >>= 1)
        m = fmaxf(m, __shfl_xor_sync(0xffffffffu, m, o));
    if ((tid & 31) == 0) red[tid >> 5] = m;
    __syncthreads();
    float bmax = red[0];
    #pragma unroll
    for (int w = 1; w < 8; w++) bmax = fmaxf(bmax, red[w]);
    __syncthreads();

    float s = 0.f;
    #pragma unroll
    for (int j = 0; j < 4; j++) {
        float2 f = b2[tid + j * 256];
        f.x = __expf(f.x - bmax);
        f.y = __expf(f.y - bmax);
        b2[tid + j * 256] = f;
        s += f.x + f.y;
    }
    #pragma unroll
    for (int o = 16; o > 0; o >>= 1)
        s += __shfl_xor_sync(0xffffffffu, s, o);
    if ((tid & 31) == 0) red[tid >> 5] = s;
    __syncthreads();
    float tot = 0.f;
    #pragma unroll
    for (int w = 0; w < 8; w++) tot += red[w];
    const float inv = 1.f / tot;

    __half2* ph2 = reinterpret_cast<__half2*>(Ph) + (long long)blockIdx.x * (SEQ / 2);
    #pragma unroll
    for (int j = 0; j < 4; j++) {
        float2 f = b2[tid + j * 256];
        ph2[tid + j * 256] = __floats2half2_rn(f.x * inv, f.y * inv);
    }
}

// ---------------------------------------------------------------------------
extern "C" void kernel_launch(void* const* d_in, const int* in_sizes, int n_in,
                              void* d_out, int out_size)
{
    const float* x  = (const float*)d_in[0];
    const float* wq = (const float*)d_in[1];
    const float* bq = (const float*)d_in[2];
    const float* wk = (const float*)d_in[3];
    const float* bk = (const float*)d_in[4];
    const float* wv = (const float*)d_in[5];
    const float* bv = (const float*)d_in[6];
    const float* wo = (const float*)d_in[7];
    const float* bo = (const float*)d_in[8];
    float* out = (float*)d_out;

    static bool attr_done = false;
    if (!attr_done) {
        cudaFuncSetAttribute((hfs_gemm<0,3>), cudaFuncAttributeMaxDynamicSharedMemorySize, SMEM_BYTES);
        cudaFuncSetAttribute((hfs_gemm<0,2>), cudaFuncAttributeMaxDynamicSharedMemorySize, SMEM_BYTES);
        cudaFuncSetAttribute((hfs_gemm<2,3>), cudaFuncAttributeMaxDynamicSharedMemorySize, SMEM_BYTES);
        attr_done = true;
    }

    hf *xh,*xl,*wch,*wcl,*woh,*wol;
    hf *qh,*ql,*kh,*kl,*vh,*vl,*vth,*vtl,*sh,*yh,*yl;
    float *s, *py, *po;
    cudaGetSymbolAddress((void**)&xh, g_xh);   cudaGetSymbolAddress((void**)&xl, g_xl);
    cudaGetSymbolAddress((void**)&wch, g_wch); cudaGetSymbolAddress((void**)&wcl, g_wcl);
    cudaGetSymbolAddress((void**)&woh, g_woh); cudaGetSymbolAddress((void**)&wol, g_wol);
    cudaGetSymbolAddress((void**)&qh, g_qh);   cudaGetSymbolAddress((void**)&ql, g_ql);
    cudaGetSymbolAddress((void**)&kh, g_kh);   cudaGetSymbolAddress((void**)&kl, g_kl);
    cudaGetSymbolAddress((void**)&vh, g_vh);   cudaGetSymbolAddress((void**)&vl, g_vl);
    cudaGetSymbolAddress((void**)&vth, g_vth); cudaGetSymbolAddress((void**)&vtl, g_vtl);
    cudaGetSymbolAddress((void**)&s, g_s);
    cudaGetSymbolAddress((void**)&sh, g_sh);
    cudaGetSymbolAddress((void**)&yh, g_yh);   cudaGetSymbolAddress((void**)&yl, g_yl);
    cudaGetSymbolAddress((void**)&py, g_py);
    cudaGetSymbolAddress((void**)&po, g_po);

    const dim3 blk(256);

    // 0) all splits in one launch
    {
        dim3 grid(512, 5, 1);
        split_all<<<grid, blk>>>(x, wq, wk, wv, wo, xh, xl, wch, wcl, woh, wol);
    }

    // 1) fused QKV projection
    {
        dim3 grid(3 * HDIM / 128, MTOT / 128, 1);
        hfs_gemm<2,3><<<grid, blk, SMEM_BYTES>>>(
            xh, xl, wch, wcl, bq, bk, bv,
            nullptr, qh, ql, kh, kl, vh, vl,
            MTOT, 3 * HDIM, NDIM, NDIM, NDIM, HDIM, 1, 0, 0, 0, 0, 0, 0);
    }
    {
        dim3 grid(HDIM / 32, SEQ / 32, BATCH);
        transpose_split<<<grid, blk>>>(vh, vl, vth, vtl);
    }

    // 2) scores = Q K^T (fp32, 3-term)
    {
        dim3 grid(SEQ / 128, SEQ / 128, BATCH);
        hfs_gemm<0,3><<<grid, blk, SMEM_BYTES>>>(
            qh, ql, kh, kl, nullptr, nullptr, nullptr,
            s, nullptr, nullptr, nullptr, nullptr, nullptr, nullptr,
            SEQ, SEQ, HDIM, HDIM, HDIM, SEQ, 1,
            (long long)SEQ * HDIM, (long long)SEQ * HDIM, (long long)SEQ * SEQ,
            0, 0, 0);
    }

    // 3) softmax -> fp16 probs (hi plane only)
    softmax_h<<<BATCH * SEQ, blk>>>(s, sh);

    // 4) y = P V  (2-term: P plain fp16, V split; split-K=2)
    {
        dim3 grid(HDIM / 128, SEQ / 128, BATCH * 2);
        hfs_gemm<0,2><<<grid, blk, SMEM_BYTES>>>(
            sh, sh, vth, vtl, nullptr, nullptr, nullptr,
            py, nullptr, nullptr, nullptr, nullptr, nullptr, nullptr,
            SEQ, HDIM, SEQ / 2, SEQ, SEQ, HDIM, 2,
            (long long)SEQ * SEQ, (long long)HDIM * SEQ, (long long)SEQ * HDIM,
            SEQ / 2, SEQ / 2, (long long)MTOT * HDIM);
    }
    combine_split<<<512, blk>>>(py, py + (long long)MTOT * HDIM, yh, yl, MTOT * HDIM / 4);

    // 5) out = Y Wo^T + bo (3-term, split-K=2)
    {
        dim3 grid(NDIM / 128, MTOT / 128, 2);
        hfs_gemm<0,3><<<grid, blk, SMEM_BYTES>>>(
            yh, yl, woh, wol, nullptr, nullptr, nullptr,
            po, nullptr, nullptr, nullptr, nullptr, nullptr, nullptr,
            MTOT, NDIM, HDIM / 2, HDIM, HDIM, NDIM, 2,
            0, 0, 0,
            HDIM / 2, HDIM / 2, (long long)MTOT * NDIM);
    }
    combine_bias<<<512, blk>>>(po, po + (long long)MTOT * NDIM, bo, out, MTOT * NDIM / 4);
}

// round 11
// speedup vs baseline: 1.3203x; 1.0428x over previous
#include <cuda_runtime.h>
#include <cuda_fp16.h>
#include <stdint.h>
#include <math.h>

#define BATCH 4
#define SEQ   2048
#define NDIM  768
#define HDIM  768
#define MTOT  (BATCH * SEQ)
#define WSZ   (HDIM * NDIM)

typedef __half hf;

// ------------------------- scratch (allocation-free) ------------------------
__device__ __align__(16) hf    g_xh[MTOT * NDIM];
__device__ __align__(16) hf    g_xl[MTOT * NDIM];
__device__ __align__(16) hf    g_wch[3 * WSZ];   // concat wq|wk|wv planes
__device__ __align__(16) hf    g_wcl[3 * WSZ];
__device__ __align__(16) hf    g_woh[WSZ];
__device__ __align__(16) hf    g_wol[WSZ];
__device__ __align__(16) hf    g_qh[MTOT * HDIM];
__device__ __align__(16) hf    g_ql[MTOT * HDIM];
__device__ __align__(16) hf    g_kh[MTOT * HDIM];
__device__ __align__(16) hf    g_kl[MTOT * HDIM];
__device__ __align__(16) hf    g_vh[MTOT * HDIM];
__device__ __align__(16) hf    g_vl[MTOT * HDIM];
__device__ __align__(16) hf    g_vth[(long long)BATCH * HDIM * SEQ];
__device__ __align__(16) hf    g_vtl[(long long)BATCH * HDIM * SEQ];
__device__ __align__(16) float g_s [(long long)BATCH * SEQ * SEQ];
__device__ __align__(16) hf    g_sh[(long long)BATCH * SEQ * SEQ];
__device__ __align__(16) hf    g_yh[MTOT * HDIM];
__device__ __align__(16) float g_py[2LL * MTOT * HDIM];   // PV split-K partials
__device__ __align__(16) float g_po[2LL * MTOT * NDIM];   // out-proj partials

// ------------------------------ helpers -------------------------------------
__device__ __forceinline__ void mma16816(float* d, const uint32_t* a, const uint32_t* b)
{
    asm volatile(
        "mma.sync.aligned.m16n8k16.row.col.f32.f16.f16.f32 "
        "{%0,%1,%2,%3},{%4,%5,%6,%7},{%8,%9},{%0,%1,%2,%3};\n"
        : "+f"(d[0]), "+f"(d[1]), "+f"(d[2]), "+f"(d[3])
        : "r"(a[0]), "r"(a[1]), "r"(a[2]), "r"(a[3]), "r"(b[0]), "r"(b[1]));
}

__device__ __forceinline__ void ldsm_x4(uint32_t* r, uint32_t addr)
{
    asm volatile("ldmatrix.sync.aligned.m8n8.x4.shared.b16 {%0,%1,%2,%3}, [%4];"
                 : "=r"(r[0]), "=r"(r[1]), "=r"(r[2]), "=r"(r[3]) : "r"(addr));
}

__device__ __forceinline__ void split1(float x, hf& h, hf& l)
{
    h = __float2half(x);
    l = __float2half(x - __half2float(h));
}

__device__ __forceinline__ void cpa16(uint32_t dst, const void* src)
{
    asm volatile("cp.async.cg.shared.global [%0], [%1], 16;\n" :: "r"(dst), "l"(src));
}
__device__ __forceinline__ void cpa_commit() { asm volatile("cp.async.commit_group;\n"); }
template <int N>
__device__ __forceinline__ void cpa_wait() { asm volatile("cp.async.wait_group %0;\n" :: "n"(N)); }

// smem geometry (uint32 words). Row = 16 data words (32 halves of k) + 4 pad.
#define RSTRIDE 20
#define PLANE_W (128 * RSTRIDE)
#define PLANE_B (PLANE_W * 4)
#define STAGE_B (4 * PLANE_B)                // 40960 B
#define SMEM_BYTES (2 * STAGE_B)             // 81920

// ---------------------------------------------------------------------------
// Split-fp16 tensor-core GEMM: C = A * B^T (+bias), split-K capable.
// EPI=0: fp32 Cf. EPI=2: fused-QKV routing to 3 split-plane dests.
// NT=3: hh + hl + lh.   NT=2: hh + hl (A-lo plane unused & not loaded).
// ---------------------------------------------------------------------------
template <int EPI, int NT>
__global__ void __launch_bounds__(256, 2) hfs_gemm(
    const hf* __restrict__ Ah, const hf* __restrict__ Al,
    const hf* __restrict__ Bh, const hf* __restrict__ Bl,
    const float* __restrict__ bias0, const float* __restrict__ bias1,
    const float* __restrict__ bias2,
    float* __restrict__ Cf,
    hf* __restrict__ Ch, hf* __restrict__ Cl,
    hf* __restrict__ C2h, hf* __restrict__ C2l,
    hf* __restrict__ C3h, hf* __restrict__ C3l,
    int M, int N, int Kloop, int lda, int ldb, int ldc,
    int nsplit,
    long long sA, long long sB, long long sC,
    long long kOffA, long long kOffB, long long sSplit)
{
    extern __shared__ uint32_t smem[];

    const int bz = blockIdx.z;
    const int batch = bz / nsplit;
    const int split = bz - batch * nsplit;

    Ah += (long long)batch * sA + split * kOffA;
    Al += (long long)batch * sA + split * kOffA;
    Bh += (long long)batch * sB + split * kOffB;
    Bl += (long long)batch * sB + split * kOffB;
    if (EPI == 0) Cf += (long long)batch * sC + split * sSplit;

    const int tid  = threadIdx.x;
    const int lane = tid & 31;
    const int warp = tid >> 5;
    const int bm = blockIdx.y * 128;
    const int bn = blockIdx.x * 128;
    const int wm = (warp & 1) * 64;
    const int wn = (warp >> 1) * 32;
    const int r = lane >> 2;
    const int c = lane & 3;

    // ---- loader mapping: thread -> row=tid/2, two 16B chunks per plane ----
    const int ld_row = tid >> 1;
    const int ld_c0  = (tid & 1) * 2;
    const hf* pAh = Ah + (long long)(bm + ld_row) * lda + ld_c0 * 8;
    const hf* pAl = Al + (long long)(bm + ld_row) * lda + ld_c0 * 8;
    const hf* pBh = Bh + (long long)(bn + ld_row) * ldb + ld_c0 * 8;
    const hf* pBl = Bl + (long long)(bn + ld_row) * ldb + ld_c0 * 8;

    uint32_t smem_u32;
    asm("{ .reg .u64 t; cvta.to.shared.u64 t, %1; cvt.u32.u64 %0, t; }"
        : "=r"(smem_u32) : "l"(smem));
    const uint32_t dst_base = smem_u32 + (ld_row * RSTRIDE + 4 * ld_c0) * 4;

    auto load_stage = [&](int stage, int k0) {
        const uint32_t d = dst_base + stage * STAGE_B;
        cpa16(d,                pAh + k0);
        cpa16(d + 16,           pAh + k0 + 8);
        if (NT == 3) {
            cpa16(d + PLANE_B,      pAl + k0);
            cpa16(d + PLANE_B + 16, pAl + k0 + 8);
        }
        cpa16(d + 2 * PLANE_B,      pBh + k0);
        cpa16(d + 2 * PLANE_B + 16, pBh + k0 + 8);
        cpa16(d + 3 * PLANE_B,      pBl + k0);
        cpa16(d + 3 * PLANE_B + 16, pBl + k0 + 8);
    };

    const uint32_t aOff = (((wm + (lane & 15)) * RSTRIDE + ((lane >> 4) << 2)) << 2);
    const uint32_t bOff = (((wn + (lane & 7) + ((lane >> 4) << 3)) * RSTRIDE
                            + (((lane >> 3) & 1) << 2)) << 2);

    float acc[4][4][4];
    #pragma unroll
    for (int i = 0; i < 4; i++)
        #pragma unroll
        for (int j = 0; j < 4; j++)
            #pragma unroll
            for (int e = 0; e < 4; e++) acc[i][j][e] = 0.f;

    const int T = Kloop / 32;

    load_stage(0, 0);  cpa_commit();
    if (T > 1) load_stage(1, 32);
    cpa_commit();

    for (int t = 0; t < T; t++) {
        cpa_wait<1>();
        __syncthreads();

        const uint32_t stage_base = smem_u32 + (t & 1) * STAGE_B;
        const uint32_t aBaseH = stage_base + aOff;
        const uint32_t aBaseL = aBaseH + PLANE_B;
        const uint32_t bBaseH = stage_base + 2 * PLANE_B + bOff;
        const uint32_t bBaseL = bBaseH + PLANE_B;

        #pragma unroll
        for (int ks = 0; ks < 2; ks++) {
            const uint32_t kb = ks * 32;
            uint32_t aH[4][4], aL[4][4], bH[4][2], bL[4][2];
            #pragma unroll
            for (int mi = 0; mi < 4; mi++) {
                ldsm_x4(aH[mi], aBaseH + mi * (16 * RSTRIDE * 4) + kb);
                if (NT == 3)
                    ldsm_x4(aL[mi], aBaseL + mi * (16 * RSTRIDE * 4) + kb);
            }
            #pragma unroll
            for (int np = 0; np < 2; np++) {
                uint32_t th[4], tl[4];
                ldsm_x4(th, bBaseH + np * (16 * RSTRIDE * 4) + kb);
                ldsm_x4(tl, bBaseL + np * (16 * RSTRIDE * 4) + kb);
                bH[2*np][0] = th[0]; bH[2*np][1] = th[1];
                bH[2*np+1][0] = th[2]; bH[2*np+1][1] = th[3];
                bL[2*np][0] = tl[0]; bL[2*np][1] = tl[1];
                bL[2*np+1][0] = tl[2]; bL[2*np+1][1] = tl[3];
            }
            #pragma unroll
            for (int mi = 0; mi < 4; mi++)
                #pragma unroll
                for (int ni = 0; ni < 4; ni++) {
                    mma16816(acc[mi][ni], aH[mi], bH[ni]);
                    mma16816(acc[mi][ni], aH[mi], bL[ni]);
                    if (NT == 3)
                        mma16816(acc[mi][ni], aL[mi], bH[ni]);
                }
        }
        __syncthreads();

        if (t + 2 < T) load_stage(t & 1, (t + 2) * 32);
        cpa_commit();
    }

    // ---------------- epilogue ----------------
    const float* bias = bias0;
    hf* dh = Ch; hf* dl = Cl;
    int cb = bn;
    int stride = ldc;
    if (EPI == 2) {
        const int seg = bn / 768;
        cb = bn - seg * 768;
        stride = 768;
        if (seg == 1) { bias = bias1; dh = C2h; dl = C2l; }
        else if (seg == 2) { bias = bias2; dh = C3h; dl = C3l; }
    }

    #pragma unroll
    for (int mi = 0; mi < 4; mi++)
        #pragma unroll
        for (int ni = 0; ni < 4; ni++) {
            const int row = bm + wm + mi * 16 + r;
            const int col = cb + wn + ni * 8 + 2 * c;
            float v00 = acc[mi][ni][0], v01 = acc[mi][ni][1];
            float v10 = acc[mi][ni][2], v11 = acc[mi][ni][3];
            if (EPI != 0 && bias) {
                const float b0 = bias[col], b1 = bias[col + 1];
                v00 += b0; v01 += b1; v10 += b0; v11 += b1;
            }
            if (EPI == 0) {
                *reinterpret_cast<float2*>(Cf + (long long)row * stride + col)
                    = make_float2(v00, v01);
                *reinterpret_cast<float2*>(Cf + (long long)(row + 8) * stride + col)
                    = make_float2(v10, v11);
            } else {
                hf h0, l0, h1, l1;
                split1(v00, h0, l0); split1(v01, h1, l1);
                *reinterpret_cast<__half2*>(dh + (long long)row * stride + col)
                    = __halves2half2(h0, h1);
                *reinterpret_cast<__half2*>(dl + (long long)row * stride + col)
                    = __halves2half2(l0, l1);
                split1(v10, h0, l0); split1(v11, h1, l1);
                *reinterpret_cast<__half2*>(dh + (long long)(row + 8) * stride + col)
                    = __halves2half2(h0, h1);
                *reinterpret_cast<__half2*>(dl + (long long)(row + 8) * stride + col)
                    = __halves2half2(l0, l1);
            }
        }
}

// ---------------------------------------------------------------------------
// All input splits in ONE launch. grid.y selects the segment.
// ---------------------------------------------------------------------------
__global__ void __launch_bounds__(256) split_all(
    const float* __restrict__ x,  const float* __restrict__ wq,
    const float* __restrict__ wk, const float* __restrict__ wv,
    const float* __restrict__ wo,
    hf* __restrict__ xh, hf* __restrict__ xl,
    hf* __restrict__ wch, hf* __restrict__ wcl,
    hf* __restrict__ woh, hf* __restrict__ wol)
{
    const float* in; hf *h, *l; int n4;
    switch (blockIdx.y) {
        case 0: in = x;  h = xh;            l = xl;            n4 = MTOT * NDIM / 4; break;
        case 1: in = wq; h = wch;           l = wcl;           n4 = WSZ / 4; break;
        case 2: in = wk; h = wch + WSZ;     l = wcl + WSZ;     n4 = WSZ / 4; break;
        case 3: in = wv; h = wch + 2 * WSZ; l = wcl + 2 * WSZ; n4 = WSZ / 4; break;
        default:in = wo; h = woh;           l = wol;           n4 = WSZ / 4; break;
    }
    for (int i = blockIdx.x * blockDim.x + threadIdx.x; i < n4;
         i += gridDim.x * blockDim.x) {
        float4 v = reinterpret_cast<const float4*>(in)[i];
        hf h0,l0,h1,l1,h2,l2,h3,l3;
        split1(v.x, h0, l0); split1(v.y, h1, l1);
        split1(v.z, h2, l2); split1(v.w, h3, l3);
        reinterpret_cast<__half2*>(h)[2 * i]     = __halves2half2(h0, h1);
        reinterpret_cast<__half2*>(h)[2 * i + 1] = __halves2half2(h2, h3);
        reinterpret_cast<__half2*>(l)[2 * i]     = __halves2half2(l0, l1);
        reinterpret_cast<__half2*>(l)[2 * i + 1] = __halves2half2(l2, l3);
    }
}

// ---------------------------------------------------------------------------
// combine split-K partials -> single fp16 plane (y hi; lo dropped by design)
// ---------------------------------------------------------------------------
__global__ void __launch_bounds__(256) combine_h(
    const float* __restrict__ p0, const float* __restrict__ p1,
    hf* __restrict__ h, int n4)
{
    for (int i = blockIdx.x * blockDim.x + threadIdx.x; i < n4;
         i += gridDim.x * blockDim.x) {
        float4 a = reinterpret_cast<const float4*>(p0)[i];
        float4 b = reinterpret_cast<const float4*>(p1)[i];
        a.x += b.x; a.y += b.y; a.z += b.z; a.w += b.w;
        reinterpret_cast<__half2*>(h)[2 * i]     = __floats2half2_rn(a.x, a.y);
        reinterpret_cast<__half2*>(h)[2 * i + 1] = __floats2half2_rn(a.z, a.w);
    }
}

// ---------------------------------------------------------------------------
__global__ void __launch_bounds__(256) combine_bias(
    const float* __restrict__ p0, const float* __restrict__ p1,
    const float* __restrict__ bias, float* __restrict__ out, int n4)
{
    for (int i = blockIdx.x * blockDim.x + threadIdx.x; i < n4;
         i += gridDim.x * blockDim.x) {
        float4 a = reinterpret_cast<const float4*>(p0)[i];
        float4 b = reinterpret_cast<const float4*>(p1)[i];
        float4 bb = reinterpret_cast<const float4*>(bias)[i % (NDIM / 4)];
        a.x += b.x + bb.x; a.y += b.y + bb.y;
        a.z += b.z + bb.z; a.w += b.w + bb.w;
        reinterpret_cast<float4*>(out)[i] = a;
    }
}

// ---------------------------------------------------------------------------
__global__ void __launch_bounds__(256) transpose_split(
    const hf* __restrict__ Vh, const hf* __restrict__ Vl,
    hf* __restrict__ Th, hf* __restrict__ Tl)
{
    __shared__ float tile[32][33];
    const int b  = blockIdx.z;
    const int h0 = blockIdx.x * 32;
    const int s0 = blockIdx.y * 32;
    const int tx = threadIdx.x & 31;
    const int ty = threadIdx.x >> 5;

    #pragma unroll
    for (int j = 0; j < 4; j++) {
        const int s = s0 + ty + j * 8;
        const long long i = (long long)(b * SEQ + s) * HDIM + h0 + tx;
        tile[ty + j * 8][tx] = __half2float(Vh[i]) + __half2float(Vl[i]);
    }
    __syncthreads();
    #pragma unroll
    for (int j = 0; j < 4; j++) {
        const int h = h0 + ty + j * 8;
        const float v = tile[tx][ty + j * 8];
        hf hi, lo; split1(v, hi, lo);
        const long long o = ((long long)b * HDIM + h) * SEQ + s0 + tx;
        Th[o] = hi; Tl[o] = lo;
    }
}

// ---------------------------------------------------------------------------
// Row softmax: fp32 scores -> fp16 probs (hi plane only; PV uses 2-term)
// ---------------------------------------------------------------------------
__global__ void __launch_bounds__(256) softmax_h(
    const float* __restrict__ S, hf* __restrict__ Ph)
{
    __shared__ float buf[SEQ];
    __shared__ float red[8];

    const int tid = threadIdx.x;
    const float2* row2 = reinterpret_cast<const float2*>(S + (long long)blockIdx.x * SEQ);
    float2* b2 = reinterpret_cast<float2*>(buf);

    float m = -1e30f;
    #pragma unroll
    for (int j = 0; j < 4; j++) {
        float2 f = row2[tid + j * 256];
        b2[tid + j * 256] = f;
        m = fmaxf(m, fmaxf(f.x, f.y));
    }
    #pragma unroll
    for (int o = 16; o > 0; o >>= 1)
        m = fmaxf(m, __shfl_xor_sync(0xffffffffu, m, o));
    if ((tid & 31) == 0) red[tid >> 5] = m;
    __syncthreads();
    float bmax = red[0];
    #pragma unroll
    for (int w = 1; w < 8; w++) bmax = fmaxf(bmax, red[w]);
    __syncthreads();

    float s = 0.f;
    #pragma unroll
    for (int j = 0; j < 4; j++) {
        float2 f = b2[tid + j * 256];
        f.x = __expf(f.x - bmax);
        f.y = __expf(f.y - bmax);
        b2[tid + j * 256] = f;
        s += f.x + f.y;
    }
    #pragma unroll
    for (int o = 16; o > 0; o >>= 1)
        s += __shfl_xor_sync(0xffffffffu, s, o);
    if ((tid & 31) == 0) red[tid >> 5] = s;
    __syncthreads();
    float tot = 0.f;
    #pragma unroll
    for (int w = 0; w < 8; w++) tot += red[w];
    const float inv = 1.f / tot;

    __half2* ph2 = reinterpret_cast<__half2*>(Ph) + (long long)blockIdx.x * (SEQ / 2);
    #pragma unroll
    for (int j = 0; j < 4; j++) {
        float2 f = b2[tid + j * 256];
        ph2[tid + j * 256] = __floats2half2_rn(f.x * inv, f.y * inv);
    }
}

// ---------------------------------------------------------------------------
extern "C" void kernel_launch(void* const* d_in, const int* in_sizes, int n_in,
                              void* d_out, int out_size)
{
    const float* x  = (const float*)d_in[0];
    const float* wq = (const float*)d_in[1];
    const float* bq = (const float*)d_in[2];
    const float* wk = (const float*)d_in[3];
    const float* bk = (const float*)d_in[4];
    const float* wv = (const float*)d_in[5];
    const float* bv = (const float*)d_in[6];
    const float* wo = (const float*)d_in[7];
    const float* bo = (const float*)d_in[8];
    float* out = (float*)d_out;

    static bool attr_done = false;
    if (!attr_done) {
        cudaFuncSetAttribute((hfs_gemm<0,3>), cudaFuncAttributeMaxDynamicSharedMemorySize, SMEM_BYTES);
        cudaFuncSetAttribute((hfs_gemm<0,2>), cudaFuncAttributeMaxDynamicSharedMemorySize, SMEM_BYTES);
        cudaFuncSetAttribute((hfs_gemm<2,3>), cudaFuncAttributeMaxDynamicSharedMemorySize, SMEM_BYTES);
        attr_done = true;
    }

    hf *xh,*xl,*wch,*wcl,*woh,*wol;
    hf *qh,*ql,*kh,*kl,*vh,*vl,*vth,*vtl,*sh,*yh;
    float *s, *py, *po;
    cudaGetSymbolAddress((void**)&xh, g_xh);   cudaGetSymbolAddress((void**)&xl, g_xl);
    cudaGetSymbolAddress((void**)&wch, g_wch); cudaGetSymbolAddress((void**)&wcl, g_wcl);
    cudaGetSymbolAddress((void**)&woh, g_woh); cudaGetSymbolAddress((void**)&wol, g_wol);
    cudaGetSymbolAddress((void**)&qh, g_qh);   cudaGetSymbolAddress((void**)&ql, g_ql);
    cudaGetSymbolAddress((void**)&kh, g_kh);   cudaGetSymbolAddress((void**)&kl, g_kl);
    cudaGetSymbolAddress((void**)&vh, g_vh);   cudaGetSymbolAddress((void**)&vl, g_vl);
    cudaGetSymbolAddress((void**)&vth, g_vth); cudaGetSymbolAddress((void**)&vtl, g_vtl);
    cudaGetSymbolAddress((void**)&s, g_s);
    cudaGetSymbolAddress((void**)&sh, g_sh);
    cudaGetSymbolAddress((void**)&yh, g_yh);
    cudaGetSymbolAddress((void**)&py, g_py);
    cudaGetSymbolAddress((void**)&po, g_po);

    const dim3 blk(256);

    // 0) all splits in one launch
    {
        dim3 grid(512, 5, 1);
        split_all<<<grid, blk>>>(x, wq, wk, wv, wo, xh, xl, wch, wcl, woh, wol);
    }

    // 1) fused QKV projection
    {
        dim3 grid(3 * HDIM / 128, MTOT / 128, 1);
        hfs_gemm<2,3><<<grid, blk, SMEM_BYTES>>>(
            xh, xl, wch, wcl, bq, bk, bv,
            nullptr, qh, ql, kh, kl, vh, vl,
            MTOT, 3 * HDIM, NDIM, NDIM, NDIM, HDIM, 1, 0, 0, 0, 0, 0, 0);
    }
    {
        dim3 grid(HDIM / 32, SEQ / 32, BATCH);
        transpose_split<<<grid, blk>>>(vh, vl, vth, vtl);
    }

    // 2) scores = Q K^T (fp32, 3-term)
    {
        dim3 grid(SEQ / 128, SEQ / 128, BATCH);
        hfs_gemm<0,3><<<grid, blk, SMEM_BYTES>>>(
            qh, ql, kh, kl, nullptr, nullptr, nullptr,
            s, nullptr, nullptr, nullptr, nullptr, nullptr, nullptr,
            SEQ, SEQ, HDIM, HDIM, HDIM, SEQ, 1,
            (long long)SEQ * HDIM, (long long)SEQ * HDIM, (long long)SEQ * SEQ,
            0, 0, 0);
    }

    // 3) softmax -> fp16 probs (hi plane only)
    softmax_h<<<BATCH * SEQ, blk>>>(s, sh);

    // 4) y = P V  (2-term: P plain fp16, V split; split-K=2)
    {
        dim3 grid(HDIM / 128, SEQ / 128, BATCH * 2);
        hfs_gemm<0,2><<<grid, blk, SMEM_BYTES>>>(
            sh, sh, vth, vtl, nullptr, nullptr, nullptr,
            py, nullptr, nullptr, nullptr, nullptr, nullptr, nullptr,
            SEQ, HDIM, SEQ / 2, SEQ, SEQ, HDIM, 2,
            (long long)SEQ * SEQ, (long long)HDIM * SEQ, (long long)SEQ * HDIM,
            SEQ / 2, SEQ / 2, (long long)MTOT * HDIM);
    }
    combine_h<<<512, blk>>>(py, py + (long long)MTOT * HDIM, yh, MTOT * HDIM / 4);

    // 5) out = Y Wo^T + bo (2-term: Y plain fp16, Wo split; split-K=2)
    {
        dim3 grid(NDIM / 128, MTOT / 128, 2);
        hfs_gemm<0,2><<<grid, blk, SMEM_BYTES>>>(
            yh, yh, woh, wol, nullptr, nullptr, nullptr,
            po, nullptr, nullptr, nullptr, nullptr, nullptr, nullptr,
            MTOT, NDIM, HDIM / 2, HDIM, HDIM, NDIM, 2,
            0, 0, 0,
            HDIM / 2, HDIM / 2, (long long)MTOT * NDIM);
    }
    combine_bias<<<512, blk>>>(po, po + (long long)MTOT * NDIM, bo, out, MTOT * NDIM / 4);
}

// round 12
// speedup vs baseline: 1.4036x; 1.0631x over previous
#include <cuda_runtime.h>
#include <cuda_fp16.h>
#include <stdint.h>
#include <math.h>

#define BATCH 4
#define SEQ   2048
#define NDIM  768
#define HDIM  768
#define MTOT  (BATCH * SEQ)
#define WSZ   (HDIM * NDIM)

typedef __half hf;

// ------------------------- scratch (allocation-free) ------------------------
__device__ __align__(16) hf    g_xh[MTOT * NDIM];
__device__ __align__(16) hf    g_xl[MTOT * NDIM];
__device__ __align__(16) hf    g_wch[3 * WSZ];   // concat wq|wk|wv planes
__device__ __align__(16) hf    g_wcl[3 * WSZ];
__device__ __align__(16) hf    g_woh[WSZ];
__device__ __align__(16) hf    g_wol[WSZ];
__device__ __align__(16) hf    g_qh[MTOT * HDIM];
__device__ __align__(16) hf    g_ql[MTOT * HDIM];
__device__ __align__(16) hf    g_kh[MTOT * HDIM];
__device__ __align__(16) hf    g_kl[MTOT * HDIM];
__device__ __align__(16) hf    g_vh[MTOT * HDIM];
__device__ __align__(16) hf    g_vl[MTOT * HDIM];
__device__ __align__(16) hf    g_vth[(long long)BATCH * HDIM * SEQ];
__device__ __align__(16) float g_s [(long long)BATCH * SEQ * SEQ];
__device__ __align__(16) hf    g_sh[(long long)BATCH * SEQ * SEQ];
__device__ __align__(16) hf    g_yh[MTOT * HDIM];
__device__ __align__(16) float g_py[2LL * MTOT * HDIM];   // PV split-K partials
__device__ __align__(16) float g_po[2LL * MTOT * NDIM];   // out-proj partials

// ------------------------------ helpers -------------------------------------
__device__ __forceinline__ void mma16816(float* d, const uint32_t* a, const uint32_t* b)
{
    asm volatile(
        "mma.sync.aligned.m16n8k16.row.col.f32.f16.f16.f32 "
        "{%0,%1,%2,%3},{%4,%5,%6,%7},{%8,%9},{%0,%1,%2,%3};\n"
        : "+f"(d[0]), "+f"(d[1]), "+f"(d[2]), "+f"(d[3])
        : "r"(a[0]), "r"(a[1]), "r"(a[2]), "r"(a[3]), "r"(b[0]), "r"(b[1]));
}

__device__ __forceinline__ void ldsm_x4(uint32_t* r, uint32_t addr)
{
    asm volatile("ldmatrix.sync.aligned.m8n8.x4.shared.b16 {%0,%1,%2,%3}, [%4];"
                 : "=r"(r[0]), "=r"(r[1]), "=r"(r[2]), "=r"(r[3]) : "r"(addr));
}

__device__ __forceinline__ void split1(float x, hf& h, hf& l)
{
    h = __float2half(x);
    l = __float2half(x - __half2float(h));
}

__device__ __forceinline__ void cpa16(uint32_t dst, const void* src)
{
    asm volatile("cp.async.cg.shared.global [%0], [%1], 16;\n" :: "r"(dst), "l"(src));
}
__device__ __forceinline__ void cpa_commit() { asm volatile("cp.async.commit_group;\n"); }
template <int N>
__device__ __forceinline__ void cpa_wait() { asm volatile("cp.async.wait_group %0;\n" :: "n"(N)); }

// smem geometry (uint32 words). Row = 16 data words (32 halves of k) + 4 pad.
#define RSTRIDE 20
#define PLANE_W (128 * RSTRIDE)
#define PLANE_B (PLANE_W * 4)
#define STAGE_B (4 * PLANE_B)                // 40960 B
#define SMEM_BYTES (2 * STAGE_B)             // 81920

// ---------------------------------------------------------------------------
// Split-fp16 tensor-core GEMM: C = A * B^T (+bias), split-K capable.
// EPI=0: fp32 Cf. EPI=2: fused-QKV routing to 3 split-plane dests.
// Term selection:
//   NT=1 : hh only          (A hi, B hi)
//   NT=2 : hh + hl          (A hi, B hi+lo)
//   NT=3 : hh + hl + lh     (A hi+lo, B hi+lo)
//   NT=23: QKV fused — B split always; A split for q/k segments, A-hi for v.
// ---------------------------------------------------------------------------
template <int EPI, int NT>
__global__ void __launch_bounds__(256, 2) hfs_gemm(
    const hf* __restrict__ Ah, const hf* __restrict__ Al,
    const hf* __restrict__ Bh, const hf* __restrict__ Bl,
    const float* __restrict__ bias0, const float* __restrict__ bias1,
    const float* __restrict__ bias2,
    float* __restrict__ Cf,
    hf* __restrict__ Ch, hf* __restrict__ Cl,
    hf* __restrict__ C2h, hf* __restrict__ C2l,
    hf* __restrict__ C3h, hf* __restrict__ C3l,
    int M, int N, int Kloop, int lda, int ldb, int ldc,
    int nsplit,
    long long sA, long long sB, long long sC,
    long long kOffA, long long kOffB, long long sSplit)
{
    extern __shared__ uint32_t smem[];

    const int bz = blockIdx.z;
    const int batch = bz / nsplit;
    const int split = bz - batch * nsplit;

    Ah += (long long)batch * sA + split * kOffA;
    Al += (long long)batch * sA + split * kOffA;
    Bh += (long long)batch * sB + split * kOffB;
    Bl += (long long)batch * sB + split * kOffB;
    if (EPI == 0) Cf += (long long)batch * sC + split * sSplit;

    const int tid  = threadIdx.x;
    const int lane = tid & 31;
    const int warp = tid >> 5;
    const int bm = blockIdx.y * 128;
    const int bn = blockIdx.x * 128;
    const int wm = (warp & 1) * 64;
    const int wn = (warp >> 1) * 32;
    const int r = lane >> 2;
    const int c = lane & 3;

    const int seg = (EPI == 2) ? (bn / 768) : 0;
    // term flags (CTA-uniform)
    const bool aLo = (NT == 3) || (NT == 23 && seg < 2);
    constexpr bool bLo = (NT >= 2);   // NT=2,3,23

    // ---- loader mapping: thread -> row=tid/2, two 16B chunks per plane ----
    const int ld_row = tid >> 1;
    const int ld_c0  = (tid & 1) * 2;
    const hf* pAh = Ah + (long long)(bm + ld_row) * lda + ld_c0 * 8;
    const hf* pAl = Al + (long long)(bm + ld_row) * lda + ld_c0 * 8;
    const hf* pBh = Bh + (long long)(bn + ld_row) * ldb + ld_c0 * 8;
    const hf* pBl = Bl + (long long)(bn + ld_row) * ldb + ld_c0 * 8;

    uint32_t smem_u32;
    asm("{ .reg .u64 t; cvta.to.shared.u64 t, %1; cvt.u32.u64 %0, t; }"
        : "=r"(smem_u32) : "l"(smem));
    const uint32_t dst_base = smem_u32 + (ld_row * RSTRIDE + 4 * ld_c0) * 4;

    auto load_stage = [&](int stage, int k0) {
        const uint32_t d = dst_base + stage * STAGE_B;
        cpa16(d,                pAh + k0);
        cpa16(d + 16,           pAh + k0 + 8);
        if (aLo) {
            cpa16(d + PLANE_B,      pAl + k0);
            cpa16(d + PLANE_B + 16, pAl + k0 + 8);
        }
        cpa16(d + 2 * PLANE_B,      pBh + k0);
        cpa16(d + 2 * PLANE_B + 16, pBh + k0 + 8);
        if (bLo) {
            cpa16(d + 3 * PLANE_B,      pBl + k0);
            cpa16(d + 3 * PLANE_B + 16, pBl + k0 + 8);
        }
    };

    const uint32_t aOff = (((wm + (lane & 15)) * RSTRIDE + ((lane >> 4) << 2)) << 2);
    const uint32_t bOff = (((wn + (lane & 7) + ((lane >> 4) << 3)) * RSTRIDE
                            + (((lane >> 3) & 1) << 2)) << 2);

    float acc[4][4][4];
    #pragma unroll
    for (int i = 0; i < 4; i++)
        #pragma unroll
        for (int j = 0; j < 4; j++)
            #pragma unroll
            for (int e = 0; e < 4; e++) acc[i][j][e] = 0.f;

    const int T = Kloop / 32;

    load_stage(0, 0);  cpa_commit();
    if (T > 1) load_stage(1, 32);
    cpa_commit();

    for (int t = 0; t < T; t++) {
        cpa_wait<1>();
        __syncthreads();

        const uint32_t stage_base = smem_u32 + (t & 1) * STAGE_B;
        const uint32_t aBaseH = stage_base + aOff;
        const uint32_t aBaseL = aBaseH + PLANE_B;
        const uint32_t bBaseH = stage_base + 2 * PLANE_B + bOff;
        const uint32_t bBaseL = bBaseH + PLANE_B;

        #pragma unroll
        for (int ks = 0; ks < 2; ks++) {
            const uint32_t kb = ks * 32;
            uint32_t aH[4][4], aL[4][4], bH[4][2], bL[4][2];
            #pragma unroll
            for (int mi = 0; mi < 4; mi++) {
                ldsm_x4(aH[mi], aBaseH + mi * (16 * RSTRIDE * 4) + kb);
                if (aLo)
                    ldsm_x4(aL[mi], aBaseL + mi * (16 * RSTRIDE * 4) + kb);
            }
            #pragma unroll
            for (int np = 0; np < 2; np++) {
                uint32_t th[4];
                ldsm_x4(th, bBaseH + np * (16 * RSTRIDE * 4) + kb);
                bH[2*np][0] = th[0]; bH[2*np][1] = th[1];
                bH[2*np+1][0] = th[2]; bH[2*np+1][1] = th[3];
                if (bLo) {
                    uint32_t tl[4];
                    ldsm_x4(tl, bBaseL + np * (16 * RSTRIDE * 4) + kb);
                    bL[2*np][0] = tl[0]; bL[2*np][1] = tl[1];
                    bL[2*np+1][0] = tl[2]; bL[2*np+1][1] = tl[3];
                }
            }
            #pragma unroll
            for (int mi = 0; mi < 4; mi++)
                #pragma unroll
                for (int ni = 0; ni < 4; ni++) {
                    mma16816(acc[mi][ni], aH[mi], bH[ni]);
                    if (bLo) mma16816(acc[mi][ni], aH[mi], bL[ni]);
                    if (aLo) mma16816(acc[mi][ni], aL[mi], bH[ni]);
                }
        }
        __syncthreads();

        if (t + 2 < T) load_stage(t & 1, (t + 2) * 32);
        cpa_commit();
    }

    // ---------------- epilogue ----------------
    const float* bias = bias0;
    hf* dh = Ch; hf* dl = Cl;
    int cb = bn;
    int stride = ldc;
    if (EPI == 2) {
        cb = bn - seg * 768;
        stride = 768;
        if (seg == 1) { bias = bias1; dh = C2h; dl = C2l; }
        else if (seg == 2) { bias = bias2; dh = C3h; dl = C3l; }
    }

    #pragma unroll
    for (int mi = 0; mi < 4; mi++)
        #pragma unroll
        for (int ni = 0; ni < 4; ni++) {
            const int row = bm + wm + mi * 16 + r;
            const int col = cb + wn + ni * 8 + 2 * c;
            float v00 = acc[mi][ni][0], v01 = acc[mi][ni][1];
            float v10 = acc[mi][ni][2], v11 = acc[mi][ni][3];
            if (EPI != 0 && bias) {
                const float b0 = bias[col], b1 = bias[col + 1];
                v00 += b0; v01 += b1; v10 += b0; v11 += b1;
            }
            if (EPI == 0) {
                *reinterpret_cast<float2*>(Cf + (long long)row * stride + col)
                    = make_float2(v00, v01);
                *reinterpret_cast<float2*>(Cf + (long long)(row + 8) * stride + col)
                    = make_float2(v10, v11);
            } else {
                hf h0, l0, h1, l1;
                split1(v00, h0, l0); split1(v01, h1, l1);
                *reinterpret_cast<__half2*>(dh + (long long)row * stride + col)
                    = __halves2half2(h0, h1);
                *reinterpret_cast<__half2*>(dl + (long long)row * stride + col)
                    = __halves2half2(l0, l1);
                split1(v10, h0, l0); split1(v11, h1, l1);
                *reinterpret_cast<__half2*>(dh + (long long)(row + 8) * stride + col)
                    = __halves2half2(h0, h1);
                *reinterpret_cast<__half2*>(dl + (long long)(row + 8) * stride + col)
                    = __halves2half2(l0, l1);
            }
        }
}

// ---------------------------------------------------------------------------
// All input splits in ONE launch. grid.y selects the segment.
// ---------------------------------------------------------------------------
__global__ void __launch_bounds__(256) split_all(
    const float* __restrict__ x,  const float* __restrict__ wq,
    const float* __restrict__ wk, const float* __restrict__ wv,
    const float* __restrict__ wo,
    hf* __restrict__ xh, hf* __restrict__ xl,
    hf* __restrict__ wch, hf* __restrict__ wcl,
    hf* __restrict__ woh, hf* __restrict__ wol)
{
    const float* in; hf *h, *l; int n4;
    switch (blockIdx.y) {
        case 0: in = x;  h = xh;            l = xl;            n4 = MTOT * NDIM / 4; break;
        case 1: in = wq; h = wch;           l = wcl;           n4 = WSZ / 4; break;
        case 2: in = wk; h = wch + WSZ;     l = wcl + WSZ;     n4 = WSZ / 4; break;
        case 3: in = wv; h = wch + 2 * WSZ; l = wcl + 2 * WSZ; n4 = WSZ / 4; break;
        default:in = wo; h = woh;           l = wol;           n4 = WSZ / 4; break;
    }
    for (int i = blockIdx.x * blockDim.x + threadIdx.x; i < n4;
         i += gridDim.x * blockDim.x) {
        float4 v = reinterpret_cast<const float4*>(in)[i];
        hf h0,l0,h1,l1,h2,l2,h3,l3;
        split1(v.x, h0, l0); split1(v.y, h1, l1);
        split1(v.z, h2, l2); split1(v.w, h3, l3);
        reinterpret_cast<__half2*>(h)[2 * i]     = __halves2half2(h0, h1);
        reinterpret_cast<__half2*>(h)[2 * i + 1] = __halves2half2(h2, h3);
        reinterpret_cast<__half2*>(l)[2 * i]     = __halves2half2(l0, l1);
        reinterpret_cast<__half2*>(l)[2 * i + 1] = __halves2half2(l2, l3);
    }
}

// ---------------------------------------------------------------------------
// combine split-K partials -> single fp16 plane (y hi)
// ---------------------------------------------------------------------------
__global__ void __launch_bounds__(256) combine_h(
    const float* __restrict__ p0, const float* __restrict__ p1,
    hf* __restrict__ h, int n4)
{
    for (int i = blockIdx.x * blockDim.x + threadIdx.x; i < n4;
         i += gridDim.x * blockDim.x) {
        float4 a = reinterpret_cast<const float4*>(p0)[i];
        float4 b = reinterpret_cast<const float4*>(p1)[i];
        a.x += b.x; a.y += b.y; a.z += b.z; a.w += b.w;
        reinterpret_cast<__half2*>(h)[2 * i]     = __floats2half2_rn(a.x, a.y);
        reinterpret_cast<__half2*>(h)[2 * i + 1] = __floats2half2_rn(a.z, a.w);
    }
}

// ---------------------------------------------------------------------------
__global__ void __launch_bounds__(256) combine_bias(
    const float* __restrict__ p0, const float* __restrict__ p1,
    const float* __restrict__ bias, float* __restrict__ out, int n4)
{
    for (int i = blockIdx.x * blockDim.x + threadIdx.x; i < n4;
         i += gridDim.x * blockDim.x) {
        float4 a = reinterpret_cast<const float4*>(p0)[i];
        float4 b = reinterpret_cast<const float4*>(p1)[i];
        float4 bb = reinterpret_cast<const float4*>(bias)[i % (NDIM / 4)];
        a.x += b.x + bb.x; a.y += b.y + bb.y;
        a.z += b.z + bb.z; a.w += b.w + bb.w;
        reinterpret_cast<float4*>(out)[i] = a;
    }
}

// ---------------------------------------------------------------------------
// V transpose: v planes [B*SEQ, HDIM] hi/lo -> VT hi plane [B, HDIM, SEQ]
// ---------------------------------------------------------------------------
__global__ void __launch_bounds__(256) transpose_h(
    const hf* __restrict__ Vh, const hf* __restrict__ Vl,
    hf* __restrict__ Th)
{
    __shared__ float tile[32][33];
    const int b  = blockIdx.z;
    const int h0 = blockIdx.x * 32;
    const int s0 = blockIdx.y * 32;
    const int tx = threadIdx.x & 31;
    const int ty = threadIdx.x >> 5;

    #pragma unroll
    for (int j = 0; j < 4; j++) {
        const int s = s0 + ty + j * 8;
        const long long i = (long long)(b * SEQ + s) * HDIM + h0 + tx;
        tile[ty + j * 8][tx] = __half2float(Vh[i]) + __half2float(Vl[i]);
    }
    __syncthreads();
    #pragma unroll
    for (int j = 0; j < 4; j++) {
        const int h = h0 + ty + j * 8;
        const long long o = ((long long)b * HDIM + h) * SEQ + s0 + tx;
        Th[o] = __float2half(tile[tx][ty + j * 8]);
    }
}

// ---------------------------------------------------------------------------
// Row softmax: fp32 scores -> fp16 probs
// ---------------------------------------------------------------------------
__global__ void __launch_bounds__(256) softmax_h(
    const float* __restrict__ S, hf* __restrict__ Ph)
{
    __shared__ float buf[SEQ];
    __shared__ float red[8];

    const int tid = threadIdx.x;
    const float2* row2 = reinterpret_cast<const float2*>(S + (long long)blockIdx.x * SEQ);
    float2* b2 = reinterpret_cast<float2*>(buf);

    float m = -1e30f;
    #pragma unroll
    for (int j = 0; j < 4; j++) {
        float2 f = row2[tid + j * 256];
        b2[tid + j * 256] = f;
        m = fmaxf(m, fmaxf(f.x, f.y));
    }
    #pragma unroll
    for (int o = 16; o > 0; o >>= 1)
        m = fmaxf(m, __shfl_xor_sync(0xffffffffu, m, o));
    if ((tid & 31) == 0) red[tid >> 5] = m;
    __syncthreads();
    float bmax = red[0];
    #pragma unroll
    for (int w = 1; w < 8; w++) bmax = fmaxf(bmax, red[w]);
    __syncthreads();

    float s = 0.f;
    #pragma unroll
    for (int j = 0; j < 4; j++) {
        float2 f = b2[tid + j * 256];
        f.x = __expf(f.x - bmax);
        f.y = __expf(f.y - bmax);
        b2[tid + j * 256] = f;
        s += f.x + f.y;
    }
    #pragma unroll
    for (int o = 16; o > 0; o >>= 1)
        s += __shfl_xor_sync(0xffffffffu, s, o);
    if ((tid & 31) == 0) red[tid >> 5] = s;
    __syncthreads();
    float tot = 0.f;
    #pragma unroll
    for (int w = 0; w < 8; w++) tot += red[w];
    const float inv = 1.f / tot;

    __half2* ph2 = reinterpret_cast<__half2*>(Ph) + (long long)blockIdx.x * (SEQ / 2);
    #pragma unroll
    for (int j = 0; j < 4; j++) {
        float2 f = b2[tid + j * 256];
        ph2[tid + j * 256] = __floats2half2_rn(f.x * inv, f.y * inv);
    }
}

// ---------------------------------------------------------------------------
extern "C" void kernel_launch(void* const* d_in, const int* in_sizes, int n_in,
                              void* d_out, int out_size)
{
    const float* x  = (const float*)d_in[0];
    const float* wq = (const float*)d_in[1];
    const float* bq = (const float*)d_in[2];
    const float* wk = (const float*)d_in[3];
    const float* bk = (const float*)d_in[4];
    const float* wv = (const float*)d_in[5];
    const float* bv = (const float*)d_in[6];
    const float* wo = (const float*)d_in[7];
    const float* bo = (const float*)d_in[8];
    float* out = (float*)d_out;

    static bool attr_done = false;
    if (!attr_done) {
        cudaFuncSetAttribute((hfs_gemm<0,3>),  cudaFuncAttributeMaxDynamicSharedMemorySize, SMEM_BYTES);
        cudaFuncSetAttribute((hfs_gemm<0,2>),  cudaFuncAttributeMaxDynamicSharedMemorySize, SMEM_BYTES);
        cudaFuncSetAttribute((hfs_gemm<0,1>),  cudaFuncAttributeMaxDynamicSharedMemorySize, SMEM_BYTES);
        cudaFuncSetAttribute((hfs_gemm<2,23>), cudaFuncAttributeMaxDynamicSharedMemorySize, SMEM_BYTES);
        attr_done = true;
    }

    hf *xh,*xl,*wch,*wcl,*woh,*wol;
    hf *qh,*ql,*kh,*kl,*vh,*vl,*vth,*sh,*yh;
    float *s, *py, *po;
    cudaGetSymbolAddress((void**)&xh, g_xh);   cudaGetSymbolAddress((void**)&xl, g_xl);
    cudaGetSymbolAddress((void**)&wch, g_wch); cudaGetSymbolAddress((void**)&wcl, g_wcl);
    cudaGetSymbolAddress((void**)&woh, g_woh); cudaGetSymbolAddress((void**)&wol, g_wol);
    cudaGetSymbolAddress((void**)&qh, g_qh);   cudaGetSymbolAddress((void**)&ql, g_ql);
    cudaGetSymbolAddress((void**)&kh, g_kh);   cudaGetSymbolAddress((void**)&kl, g_kl);
    cudaGetSymbolAddress((void**)&vh, g_vh);   cudaGetSymbolAddress((void**)&vl, g_vl);
    cudaGetSymbolAddress((void**)&vth, g_vth);
    cudaGetSymbolAddress((void**)&s, g_s);
    cudaGetSymbolAddress((void**)&sh, g_sh);
    cudaGetSymbolAddress((void**)&yh, g_yh);
    cudaGetSymbolAddress((void**)&py, g_py);
    cudaGetSymbolAddress((void**)&po, g_po);

    const dim3 blk(256);

    // 0) all splits in one launch
    {
        dim3 grid(512, 5, 1);
        split_all<<<grid, blk>>>(x, wq, wk, wv, wo, xh, xl, wch, wcl, woh, wol);
    }

    // 1) fused QKV projection (q,k 3-term; v 2-term)
    {
        dim3 grid(3 * HDIM / 128, MTOT / 128, 1);
        hfs_gemm<2,23><<<grid, blk, SMEM_BYTES>>>(
            xh, xl, wch, wcl, bq, bk, bv,
            nullptr, qh, ql, kh, kl, vh, vl,
            MTOT, 3 * HDIM, NDIM, NDIM, NDIM, HDIM, 1, 0, 0, 0, 0, 0, 0);
    }
    {
        dim3 grid(HDIM / 32, SEQ / 32, BATCH);
        transpose_h<<<grid, blk>>>(vh, vl, vth);
    }

    // 2) scores = Q K^T (fp32, 3-term)
    {
        dim3 grid(SEQ / 128, SEQ / 128, BATCH);
        hfs_gemm<0,3><<<grid, blk, SMEM_BYTES>>>(
            qh, ql, kh, kl, nullptr, nullptr, nullptr,
            s, nullptr, nullptr, nullptr, nullptr, nullptr, nullptr,
            SEQ, SEQ, HDIM, HDIM, HDIM, SEQ, 1,
            (long long)SEQ * HDIM, (long long)SEQ * HDIM, (long long)SEQ * SEQ,
            0, 0, 0);
    }

    // 3) softmax -> fp16 probs
    softmax_h<<<BATCH * SEQ, blk>>>(s, sh);

    // 4) y = P V  (1-term: P fp16 x V^T fp16; split-K=2)
    {
        dim3 grid(HDIM / 128, SEQ / 128, BATCH * 2);
        hfs_gemm<0,1><<<grid, blk, SMEM_BYTES>>>(
            sh, sh, vth, vth, nullptr, nullptr, nullptr,
            py, nullptr, nullptr, nullptr, nullptr, nullptr, nullptr,
            SEQ, HDIM, SEQ / 2, SEQ, SEQ, HDIM, 2,
            (long long)SEQ * SEQ, (long long)HDIM * SEQ, (long long)SEQ * HDIM,
            SEQ / 2, SEQ / 2, (long long)MTOT * HDIM);
    }
    combine_h<<<512, blk>>>(py, py + (long long)MTOT * HDIM, yh, MTOT * HDIM / 4);

    // 5) out = Y Wo^T + bo (2-term: Y fp16, Wo split; split-K=2)
    {
        dim3 grid(NDIM / 128, MTOT / 128, 2);
        hfs_gemm<0,2><<<grid, blk, SMEM_BYTES>>>(
            yh, yh, woh, wol, nullptr, nullptr, nullptr,
            po, nullptr, nullptr, nullptr, nullptr, nullptr, nullptr,
            MTOT, NDIM, HDIM / 2, HDIM, HDIM, NDIM, 2,
            0, 0, 0,
            HDIM / 2, HDIM / 2, (long long)MTOT * NDIM);
    }
    combine_bias<<<512, blk>>>(po, po + (long long)MTOT * NDIM, bo, out, MTOT * NDIM / 4);
}

// round 13
// speedup vs baseline: 1.4286x; 1.0178x over previous
#include <cuda_runtime.h>
#include <cuda_fp16.h>
#include <stdint.h>
#include <math.h>

#define BATCH 4
#define SEQ   2048
#define NDIM  768
#define HDIM  768
#define MTOT  (BATCH * SEQ)
#define WSZ   (HDIM * NDIM)

typedef __half hf;

// ------------------------- scratch (allocation-free) ------------------------
__device__ __align__(16) hf    g_xh[MTOT * NDIM];
__device__ __align__(16) hf    g_xl[MTOT * NDIM];
__device__ __align__(16) hf    g_wch[3 * WSZ];   // concat wq|wk|wv planes
__device__ __align__(16) hf    g_wcl[3 * WSZ];
__device__ __align__(16) hf    g_woh[WSZ];
__device__ __align__(16) hf    g_wol[WSZ];
__device__ __align__(16) hf    g_qh[MTOT * HDIM];
__device__ __align__(16) hf    g_ql[MTOT * HDIM];
__device__ __align__(16) hf    g_kh[MTOT * HDIM];
__device__ __align__(16) hf    g_kl[MTOT * HDIM];
__device__ __align__(16) hf    g_vth[(long long)BATCH * HDIM * SEQ];
__device__ __align__(16) float g_s [(long long)BATCH * SEQ * SEQ];
__device__ __align__(16) hf    g_sh[(long long)BATCH * SEQ * SEQ];
__device__ __align__(16) hf    g_yh[MTOT * HDIM];
__device__ __align__(16) float g_py[2LL * MTOT * HDIM];   // PV split-K partials
__device__ __align__(16) float g_po[2LL * MTOT * NDIM];   // out-proj partials

// ------------------------------ helpers -------------------------------------
__device__ __forceinline__ void mma16816(float* d, const uint32_t* a, const uint32_t* b)
{
    asm volatile(
        "mma.sync.aligned.m16n8k16.row.col.f32.f16.f16.f32 "
        "{%0,%1,%2,%3},{%4,%5,%6,%7},{%8,%9},{%0,%1,%2,%3};\n"
        : "+f"(d[0]), "+f"(d[1]), "+f"(d[2]), "+f"(d[3])
        : "r"(a[0]), "r"(a[1]), "r"(a[2]), "r"(a[3]), "r"(b[0]), "r"(b[1]));
}

__device__ __forceinline__ void ldsm_x4(uint32_t* r, uint32_t addr)
{
    asm volatile("ldmatrix.sync.aligned.m8n8.x4.shared.b16 {%0,%1,%2,%3}, [%4];"
                 : "=r"(r[0]), "=r"(r[1]), "=r"(r[2]), "=r"(r[3]) : "r"(addr));
}

__device__ __forceinline__ void split1(float x, hf& h, hf& l)
{
    h = __float2half(x);
    l = __float2half(x - __half2float(h));
}

__device__ __forceinline__ void cpa16(uint32_t dst, const void* src)
{
    asm volatile("cp.async.cg.shared.global [%0], [%1], 16;\n" :: "r"(dst), "l"(src));
}
__device__ __forceinline__ void cpa_commit() { asm volatile("cp.async.commit_group;\n"); }
template <int N>
__device__ __forceinline__ void cpa_wait() { asm volatile("cp.async.wait_group %0;\n" :: "n"(N)); }

// smem geometry (uint32 words). Row = 16 data words (32 halves of k) + 4 pad.
#define RSTRIDE 20
#define PLANE_W (128 * RSTRIDE)
#define PLANE_B (PLANE_W * 4)
#define STAGE_B (4 * PLANE_B)                // 40960 B
#define SMEM_BYTES (2 * STAGE_B)             // 81920

// ---------------------------------------------------------------------------
// Split-fp16 tensor-core GEMM: C = A * B^T (+bias), split-K capable.
// EPI=0: fp32 Cf. EPI=2: fused-QKV: seg0/1 -> split q/k planes; seg2 -> v
//        written DIRECTLY TRANSPOSED (fp16) into C3h=[B,HDIM,SEQ], bias folded.
// Terms:  NT=1: hh.  NT=2: hh+hl.  NT=3: hh+hl+lh.
//         NT=23: QKV fused — q/k segs 3-term, v seg 1-term.
// ---------------------------------------------------------------------------
template <int EPI, int NT>
__global__ void __launch_bounds__(256, 2) hfs_gemm(
    const hf* __restrict__ Ah, const hf* __restrict__ Al,
    const hf* __restrict__ Bh, const hf* __restrict__ Bl,
    const float* __restrict__ bias0, const float* __restrict__ bias1,
    const float* __restrict__ bias2,
    float* __restrict__ Cf,
    hf* __restrict__ Ch, hf* __restrict__ Cl,
    hf* __restrict__ C2h, hf* __restrict__ C2l,
    hf* __restrict__ C3h, hf* __restrict__ C3l,
    int M, int N, int Kloop, int lda, int ldb, int ldc,
    int nsplit,
    long long sA, long long sB, long long sC,
    long long kOffA, long long kOffB, long long sSplit)
{
    extern __shared__ uint32_t smem[];

    const int bz = blockIdx.z;
    const int batch = bz / nsplit;
    const int split = bz - batch * nsplit;

    Ah += (long long)batch * sA + split * kOffA;
    Al += (long long)batch * sA + split * kOffA;
    Bh += (long long)batch * sB + split * kOffB;
    Bl += (long long)batch * sB + split * kOffB;
    if (EPI == 0) Cf += (long long)batch * sC + split * sSplit;

    const int tid  = threadIdx.x;
    const int lane = tid & 31;
    const int warp = tid >> 5;
    const int bm = blockIdx.y * 128;
    const int bn = blockIdx.x * 128;
    const int wm = (warp & 1) * 64;
    const int wn = (warp >> 1) * 32;
    const int r = lane >> 2;
    const int c = lane & 3;

    const int seg = (EPI == 2) ? (bn / 768) : 0;
    // term flags (CTA-uniform)
    const bool aLo = (NT == 3) || (NT == 23 && seg < 2);
    const bool bLo = (NT == 23) ? (seg < 2) : (NT >= 2);

    // ---- loader mapping: thread -> row=tid/2, two 16B chunks per plane ----
    const int ld_row = tid >> 1;
    const int ld_c0  = (tid & 1) * 2;
    const hf* pAh = Ah + (long long)(bm + ld_row) * lda + ld_c0 * 8;
    const hf* pAl = Al + (long long)(bm + ld_row) * lda + ld_c0 * 8;
    const hf* pBh = Bh + (long long)(bn + ld_row) * ldb + ld_c0 * 8;
    const hf* pBl = Bl + (long long)(bn + ld_row) * ldb + ld_c0 * 8;

    uint32_t smem_u32;
    asm("{ .reg .u64 t; cvta.to.shared.u64 t, %1; cvt.u32.u64 %0, t; }"
        : "=r"(smem_u32) : "l"(smem));
    const uint32_t dst_base = smem_u32 + (ld_row * RSTRIDE + 4 * ld_c0) * 4;

    auto load_stage = [&](int stage, int k0) {
        const uint32_t d = dst_base + stage * STAGE_B;
        cpa16(d,                pAh + k0);
        cpa16(d + 16,           pAh + k0 + 8);
        if (aLo) {
            cpa16(d + PLANE_B,      pAl + k0);
            cpa16(d + PLANE_B + 16, pAl + k0 + 8);
        }
        cpa16(d + 2 * PLANE_B,      pBh + k0);
        cpa16(d + 2 * PLANE_B + 16, pBh + k0 + 8);
        if (bLo) {
            cpa16(d + 3 * PLANE_B,      pBl + k0);
            cpa16(d + 3 * PLANE_B + 16, pBl + k0 + 8);
        }
    };

    const uint32_t aOff = (((wm + (lane & 15)) * RSTRIDE + ((lane >> 4) << 2)) << 2);
    const uint32_t bOff = (((wn + (lane & 7) + ((lane >> 4) << 3)) * RSTRIDE
                            + (((lane >> 3) & 1) << 2)) << 2);

    float acc[4][4][4];
    #pragma unroll
    for (int i = 0; i < 4; i++)
        #pragma unroll
        for (int j = 0; j < 4; j++)
            #pragma unroll
            for (int e = 0; e < 4; e++) acc[i][j][e] = 0.f;

    const int T = Kloop / 32;

    load_stage(0, 0);  cpa_commit();
    if (T > 1) load_stage(1, 32);
    cpa_commit();

    for (int t = 0; t < T; t++) {
        cpa_wait<1>();
        __syncthreads();

        const uint32_t stage_base = smem_u32 + (t & 1) * STAGE_B;
        const uint32_t aBaseH = stage_base + aOff;
        const uint32_t aBaseL = aBaseH + PLANE_B;
        const uint32_t bBaseH = stage_base + 2 * PLANE_B + bOff;
        const uint32_t bBaseL = bBaseH + PLANE_B;

        #pragma unroll
        for (int ks = 0; ks < 2; ks++) {
            const uint32_t kb = ks * 32;
            uint32_t aH[4][4], aL[4][4], bH[4][2], bL[4][2];
            #pragma unroll
            for (int mi = 0; mi < 4; mi++) {
                ldsm_x4(aH[mi], aBaseH + mi * (16 * RSTRIDE * 4) + kb);
                if (aLo)
                    ldsm_x4(aL[mi], aBaseL + mi * (16 * RSTRIDE * 4) + kb);
            }
            #pragma unroll
            for (int np = 0; np < 2; np++) {
                uint32_t th[4];
                ldsm_x4(th, bBaseH + np * (16 * RSTRIDE * 4) + kb);
                bH[2*np][0] = th[0]; bH[2*np][1] = th[1];
                bH[2*np+1][0] = th[2]; bH[2*np+1][1] = th[3];
                if (bLo) {
                    uint32_t tl[4];
                    ldsm_x4(tl, bBaseL + np * (16 * RSTRIDE * 4) + kb);
                    bL[2*np][0] = tl[0]; bL[2*np][1] = tl[1];
                    bL[2*np+1][0] = tl[2]; bL[2*np+1][1] = tl[3];
                }
            }
            #pragma unroll
            for (int mi = 0; mi < 4; mi++)
                #pragma unroll
                for (int ni = 0; ni < 4; ni++) {
                    mma16816(acc[mi][ni], aH[mi], bH[ni]);
                    if (bLo) mma16816(acc[mi][ni], aH[mi], bL[ni]);
                    if (aLo) mma16816(acc[mi][ni], aL[mi], bH[ni]);
                }
        }
        __syncthreads();

        if (t + 2 < T) load_stage(t & 1, (t + 2) * 32);
        cpa_commit();
    }

    // ---------------- epilogue ----------------
    const float* bias = bias0;
    hf* dh = Ch; hf* dl = Cl;
    int cb = bn;
    int stride = ldc;
    if (EPI == 2) {
        cb = bn - seg * 768;
        stride = 768;
        if (seg == 1) { bias = bias1; dh = C2h; dl = C2l; }
        else if (seg == 2) { bias = bias2; }
    }

    if (EPI == 2 && seg == 2) {
        // ---- v segment: bias + fp16, written TRANSPOSED into C3h[B,HDIM,SEQ]
        __syncthreads();   // all warps done with pipeline smem (LDSM complete)
        hf* st = reinterpret_cast<hf*>(smem);
        #pragma unroll
        for (int mi = 0; mi < 4; mi++)
            #pragma unroll
            for (int ni = 0; ni < 4; ni++) {
                const int rl = wm + mi * 16 + r;
                const int cl = wn + ni * 8 + 2 * c;
                const float b0 = bias[cb + cl], b1 = bias[cb + cl + 1];
                st[cl * 136 + rl]           = __float2half(acc[mi][ni][0] + b0);
                st[(cl + 1) * 136 + rl]     = __float2half(acc[mi][ni][1] + b1);
                st[cl * 136 + rl + 8]       = __float2half(acc[mi][ni][2] + b0);
                st[(cl + 1) * 136 + rl + 8] = __float2half(acc[mi][ni][3] + b1);
            }
        __syncthreads();
        const int b  = bm >> 11;          // batch (SEQ = 2048)
        const int s0 = bm & 2047;         // seq offset within batch
        const int col   = tid >> 1;       // 0..127 local h
        const int chunk = tid & 1;        // 64-row half
        const uint4* src = reinterpret_cast<const uint4*>(st + col * 136 + chunk * 64);
        uint4* dst = reinterpret_cast<uint4*>(
            C3h + ((long long)b * HDIM + cb + col) * SEQ + s0 + chunk * 64);
        #pragma unroll
        for (int i = 0; i < 8; i++) dst[i] = src[i];
        return;
    }

    #pragma unroll
    for (int mi = 0; mi < 4; mi++)
        #pragma unroll
        for (int ni = 0; ni < 4; ni++) {
            const int row = bm + wm + mi * 16 + r;
            const int col = cb + wn + ni * 8 + 2 * c;
            float v00 = acc[mi][ni][0], v01 = acc[mi][ni][1];
            float v10 = acc[mi][ni][2], v11 = acc[mi][ni][3];
            if (EPI != 0 && bias) {
                const float b0 = bias[col], b1 = bias[col + 1];
                v00 += b0; v01 += b1; v10 += b0; v11 += b1;
            }
            if (EPI == 0) {
                *reinterpret_cast<float2*>(Cf + (long long)row * stride + col)
                    = make_float2(v00, v01);
                *reinterpret_cast<float2*>(Cf + (long long)(row + 8) * stride + col)
                    = make_float2(v10, v11);
            } else {
                hf h0, l0, h1, l1;
                split1(v00, h0, l0); split1(v01, h1, l1);
                *reinterpret_cast<__half2*>(dh + (long long)row * stride + col)
                    = __halves2half2(h0, h1);
                *reinterpret_cast<__half2*>(dl + (long long)row * stride + col)
                    = __halves2half2(l0, l1);
                split1(v10, h0, l0); split1(v11, h1, l1);
                *reinterpret_cast<__half2*>(dh + (long long)(row + 8) * stride + col)
                    = __halves2half2(h0, h1);
                *reinterpret_cast<__half2*>(dl + (long long)(row + 8) * stride + col)
                    = __halves2half2(l0, l1);
            }
        }
}

// ---------------------------------------------------------------------------
// All input splits in ONE launch. grid.y selects the segment.
// ---------------------------------------------------------------------------
__global__ void __launch_bounds__(256) split_all(
    const float* __restrict__ x,  const float* __restrict__ wq,
    const float* __restrict__ wk, const float* __restrict__ wv,
    const float* __restrict__ wo,
    hf* __restrict__ xh, hf* __restrict__ xl,
    hf* __restrict__ wch, hf* __restrict__ wcl,
    hf* __restrict__ woh, hf* __restrict__ wol)
{
    const float* in; hf *h, *l; int n4;
    switch (blockIdx.y) {
        case 0: in = x;  h = xh;            l = xl;            n4 = MTOT * NDIM / 4; break;
        case 1: in = wq; h = wch;           l = wcl;           n4 = WSZ / 4; break;
        case 2: in = wk; h = wch + WSZ;     l = wcl + WSZ;     n4 = WSZ / 4; break;
        case 3: in = wv; h = wch + 2 * WSZ; l = wcl + 2 * WSZ; n4 = WSZ / 4; break;
        default:in = wo; h = woh;           l = wol;           n4 = WSZ / 4; break;
    }
    for (int i = blockIdx.x * blockDim.x + threadIdx.x; i < n4;
         i += gridDim.x * blockDim.x) {
        float4 v = reinterpret_cast<const float4*>(in)[i];
        hf h0,l0,h1,l1,h2,l2,h3,l3;
        split1(v.x, h0, l0); split1(v.y, h1, l1);
        split1(v.z, h2, l2); split1(v.w, h3, l3);
        reinterpret_cast<__half2*>(h)[2 * i]     = __halves2half2(h0, h1);
        reinterpret_cast<__half2*>(h)[2 * i + 1] = __halves2half2(h2, h3);
        reinterpret_cast<__half2*>(l)[2 * i]     = __halves2half2(l0, l1);
        reinterpret_cast<__half2*>(l)[2 * i + 1] = __halves2half2(l2, l3);
    }
}

// ---------------------------------------------------------------------------
// combine split-K partials -> single fp16 plane (y hi)
// ---------------------------------------------------------------------------
__global__ void __launch_bounds__(256) combine_h(
    const float* __restrict__ p0, const float* __restrict__ p1,
    hf* __restrict__ h, int n4)
{
    for (int i = blockIdx.x * blockDim.x + threadIdx.x; i < n4;
         i += gridDim.x * blockDim.x) {
        float4 a = reinterpret_cast<const float4*>(p0)[i];
        float4 b = reinterpret_cast<const float4*>(p1)[i];
        a.x += b.x; a.y += b.y; a.z += b.z; a.w += b.w;
        reinterpret_cast<__half2*>(h)[2 * i]     = __floats2half2_rn(a.x, a.y);
        reinterpret_cast<__half2*>(h)[2 * i + 1] = __floats2half2_rn(a.z, a.w);
    }
}

// ---------------------------------------------------------------------------
__global__ void __launch_bounds__(256) combine_bias(
    const float* __restrict__ p0, const float* __restrict__ p1,
    const float* __restrict__ bias, float* __restrict__ out, int n4)
{
    for (int i = blockIdx.x * blockDim.x + threadIdx.x; i < n4;
         i += gridDim.x * blockDim.x) {
        float4 a = reinterpret_cast<const float4*>(p0)[i];
        float4 b = reinterpret_cast<const float4*>(p1)[i];
        float4 bb = reinterpret_cast<const float4*>(bias)[i % (NDIM / 4)];
        a.x += b.x + bb.x; a.y += b.y + bb.y;
        a.z += b.z + bb.z; a.w += b.w + bb.w;
        reinterpret_cast<float4*>(out)[i] = a;
    }
}

// ---------------------------------------------------------------------------
// Row softmax: fp32 scores -> fp16 probs
// ---------------------------------------------------------------------------
__global__ void __launch_bounds__(256) softmax_h(
    const float* __restrict__ S, hf* __restrict__ Ph)
{
    __shared__ float buf[SEQ];
    __shared__ float red[8];

    const int tid = threadIdx.x;
    const float2* row2 = reinterpret_cast<const float2*>(S + (long long)blockIdx.x * SEQ);
    float2* b2 = reinterpret_cast<float2*>(buf);

    float m = -1e30f;
    #pragma unroll
    for (int j = 0; j < 4; j++) {
        float2 f = row2[tid + j * 256];
        b2[tid + j * 256] = f;
        m = fmaxf(m, fmaxf(f.x, f.y));
    }
    #pragma unroll
    for (int o = 16; o > 0; o >>= 1)
        m = fmaxf(m, __shfl_xor_sync(0xffffffffu, m, o));
    if ((tid & 31) == 0) red[tid >> 5] = m;
    __syncthreads();
    float bmax = red[0];
    #pragma unroll
    for (int w = 1; w < 8; w++) bmax = fmaxf(bmax, red[w]);
    __syncthreads();

    float s = 0.f;
    #pragma unroll
    for (int j = 0; j < 4; j++) {
        float2 f = b2[tid + j * 256];
        f.x = __expf(f.x - bmax);
        f.y = __expf(f.y - bmax);
        b2[tid + j * 256] = f;
        s += f.x + f.y;
    }
    #pragma unroll
    for (int o = 16; o > 0; o >>= 1)
        s += __shfl_xor_sync(0xffffffffu, s, o);
    if ((tid & 31) == 0) red[tid >> 5] = s;
    __syncthreads();
    float tot = 0.f;
    #pragma unroll
    for (int w = 0; w < 8; w++) tot += red[w];
    const float inv = 1.f / tot;

    __half2* ph2 = reinterpret_cast<__half2*>(Ph) + (long long)blockIdx.x * (SEQ / 2);
    #pragma unroll
    for (int j = 0; j < 4; j++) {
        float2 f = b2[tid + j * 256];
        ph2[tid + j * 256] = __floats2half2_rn(f.x * inv, f.y * inv);
    }
}

// ---------------------------------------------------------------------------
extern "C" void kernel_launch(void* const* d_in, const int* in_sizes, int n_in,
                              void* d_out, int out_size)
{
    const float* x  = (const float*)d_in[0];
    const float* wq = (const float*)d_in[1];
    const float* bq = (const float*)d_in[2];
    const float* wk = (const float*)d_in[3];
    const float* bk = (const float*)d_in[4];
    const float* wv = (const float*)d_in[5];
    const float* bv = (const float*)d_in[6];
    const float* wo = (const float*)d_in[7];
    const float* bo = (const float*)d_in[8];
    float* out = (float*)d_out;

    static bool attr_done = false;
    if (!attr_done) {
        cudaFuncSetAttribute((hfs_gemm<0,3>),  cudaFuncAttributeMaxDynamicSharedMemorySize, SMEM_BYTES);
        cudaFuncSetAttribute((hfs_gemm<0,2>),  cudaFuncAttributeMaxDynamicSharedMemorySize, SMEM_BYTES);
        cudaFuncSetAttribute((hfs_gemm<0,1>),  cudaFuncAttributeMaxDynamicSharedMemorySize, SMEM_BYTES);
        cudaFuncSetAttribute((hfs_gemm<2,23>), cudaFuncAttributeMaxDynamicSharedMemorySize, SMEM_BYTES);
        attr_done = true;
    }

    hf *xh,*xl,*wch,*wcl,*woh,*wol;
    hf *qh,*ql,*kh,*kl,*vth,*sh,*yh;
    float *s, *py, *po;
    cudaGetSymbolAddress((void**)&xh, g_xh);   cudaGetSymbolAddress((void**)&xl, g_xl);
    cudaGetSymbolAddress((void**)&wch, g_wch); cudaGetSymbolAddress((void**)&wcl, g_wcl);
    cudaGetSymbolAddress((void**)&woh, g_woh); cudaGetSymbolAddress((void**)&wol, g_wol);
    cudaGetSymbolAddress((void**)&qh, g_qh);   cudaGetSymbolAddress((void**)&ql, g_ql);
    cudaGetSymbolAddress((void**)&kh, g_kh);   cudaGetSymbolAddress((void**)&kl, g_kl);
    cudaGetSymbolAddress((void**)&vth, g_vth);
    cudaGetSymbolAddress((void**)&s, g_s);
    cudaGetSymbolAddress((void**)&sh, g_sh);
    cudaGetSymbolAddress((void**)&yh, g_yh);
    cudaGetSymbolAddress((void**)&py, g_py);
    cudaGetSymbolAddress((void**)&po, g_po);

    const dim3 blk(256);

    // 0) all splits in one launch
    {
        dim3 grid(512, 5, 1);
        split_all<<<grid, blk>>>(x, wq, wk, wv, wo, xh, xl, wch, wcl, woh, wol);
    }

    // 1) fused QKV projection (q,k 3-term; v 1-term written transposed to vth)
    {
        dim3 grid(3 * HDIM / 128, MTOT / 128, 1);
        hfs_gemm<2,23><<<grid, blk, SMEM_BYTES>>>(
            xh, xl, wch, wcl, bq, bk, bv,
            nullptr, qh, ql, kh, kl, vth, vth,
            MTOT, 3 * HDIM, NDIM, NDIM, NDIM, HDIM, 1, 0, 0, 0, 0, 0, 0);
    }

    // 2) scores = Q K^T (fp32, 3-term)
    {
        dim3 grid(SEQ / 128, SEQ / 128, BATCH);
        hfs_gemm<0,3><<<grid, blk, SMEM_BYTES>>>(
            qh, ql, kh, kl, nullptr, nullptr, nullptr,
            s, nullptr, nullptr, nullptr, nullptr, nullptr, nullptr,
            SEQ, SEQ, HDIM, HDIM, HDIM, SEQ, 1,
            (long long)SEQ * HDIM, (long long)SEQ * HDIM, (long long)SEQ * SEQ,
            0, 0, 0);
    }

    // 3) softmax -> fp16 probs
    softmax_h<<<BATCH * SEQ, blk>>>(s, sh);

    // 4) y = P V  (1-term: P fp16 x V^T fp16; split-K=2)
    {
        dim3 grid(HDIM / 128, SEQ / 128, BATCH * 2);
        hfs_gemm<0,1><<<grid, blk, SMEM_BYTES>>>(
            sh, sh, vth, vth, nullptr, nullptr, nullptr,
            py, nullptr, nullptr, nullptr, nullptr, nullptr, nullptr,
            SEQ, HDIM, SEQ / 2, SEQ, SEQ, HDIM, 2,
            (long long)SEQ * SEQ, (long long)HDIM * SEQ, (long long)SEQ * HDIM,
            SEQ / 2, SEQ / 2, (long long)MTOT * HDIM);
    }
    combine_h<<<512, blk>>>(py, py + (long long)MTOT * HDIM, yh, MTOT * HDIM / 4);

    // 5) out = Y Wo^T + bo (2-term: Y fp16, Wo split; split-K=2)
    {
        dim3 grid(NDIM / 128, MTOT / 128, 2);
        hfs_gemm<0,2><<<grid, blk, SMEM_BYTES>>>(
            yh, yh, woh, wol, nullptr, nullptr, nullptr,
            po, nullptr, nullptr, nullptr, nullptr, nullptr, nullptr,
            MTOT, NDIM, HDIM / 2, HDIM, HDIM, NDIM, 2,
            0, 0, 0,
            HDIM / 2, HDIM / 2, (long long)MTOT * NDIM);
    }
    combine_bias<<<512, blk>>>(po, po + (long long)MTOT * NDIM, bo, out, MTOT * NDIM / 4);
}

// round 14
// speedup vs baseline: 1.5084x; 1.0558x over previous
#include <cuda_runtime.h>
#include <cuda_fp16.h>
#include <stdint.h>
#include <math.h>

#define BATCH 4
#define SEQ   2048
#define NDIM  768
#define HDIM  768
#define MTOT  (BATCH * SEQ)
#define WSZ   (HDIM * NDIM)

typedef __half hf;

// ------------------------- scratch (allocation-free) ------------------------
__device__ __align__(16) hf    g_xh[MTOT * NDIM];
__device__ __align__(16) hf    g_xl[MTOT * NDIM];
__device__ __align__(16) hf    g_wch[3 * WSZ];   // concat wq|wk|wv planes
__device__ __align__(16) hf    g_wcl[3 * WSZ];
__device__ __align__(16) hf    g_woh[WSZ];
__device__ __align__(16) hf    g_wol[WSZ];
__device__ __align__(16) hf    g_qh[MTOT * HDIM];
__device__ __align__(16) hf    g_ql[MTOT * HDIM];
__device__ __align__(16) hf    g_kh[MTOT * HDIM];
__device__ __align__(16) hf    g_kl[MTOT * HDIM];
__device__ __align__(16) hf    g_vth[(long long)BATCH * HDIM * SEQ];
__device__ __align__(16) float g_s [(long long)BATCH * SEQ * SEQ];
__device__ __align__(16) hf    g_sh[(long long)BATCH * SEQ * SEQ];
__device__ __align__(16) hf    g_yh[MTOT * HDIM];
__device__ __align__(16) float g_py[2LL * MTOT * HDIM];   // PV split-K partials

// ------------------------------ helpers -------------------------------------
__device__ __forceinline__ void mma16816(float* d, const uint32_t* a, const uint32_t* b)
{
    asm volatile(
        "mma.sync.aligned.m16n8k16.row.col.f32.f16.f16.f32 "
        "{%0,%1,%2,%3},{%4,%5,%6,%7},{%8,%9},{%0,%1,%2,%3};\n"
        : "+f"(d[0]), "+f"(d[1]), "+f"(d[2]), "+f"(d[3])
        : "r"(a[0]), "r"(a[1]), "r"(a[2]), "r"(a[3]), "r"(b[0]), "r"(b[1]));
}

__device__ __forceinline__ void ldsm_x4(uint32_t* r, uint32_t addr)
{
    asm volatile("ldmatrix.sync.aligned.m8n8.x4.shared.b16 {%0,%1,%2,%3}, [%4];"
                 : "=r"(r[0]), "=r"(r[1]), "=r"(r[2]), "=r"(r[3]) : "r"(addr));
}

__device__ __forceinline__ void split1(float x, hf& h, hf& l)
{
    h = __float2half(x);
    l = __float2half(x - __half2float(h));
}

__device__ __forceinline__ void cpa16(uint32_t dst, const void* src)
{
    asm volatile("cp.async.cg.shared.global [%0], [%1], 16;\n" :: "r"(dst), "l"(src));
}
__device__ __forceinline__ void cpa_commit() { asm volatile("cp.async.commit_group;\n"); }
template <int N>
__device__ __forceinline__ void cpa_wait() { asm volatile("cp.async.wait_group %0;\n" :: "n"(N)); }

// smem geometry (uint32 words). Row = 16 data words (32 halves of k) + 4 pad.
#define RSTRIDE 20
#define PLANE_W (128 * RSTRIDE)
#define PLANE_B (PLANE_W * 4)
#define STAGE_B (4 * PLANE_B)                // 40960 B
#define SMEM_BYTES (2 * STAGE_B)             // 81920

// ---------------------------------------------------------------------------
// Split-fp16 tensor-core GEMM: C = A * B^T (+bias), split-K capable.
// EPI=0: fp32 Cf (adds bias0 if non-null).
// EPI=2: fused-QKV: seg0/1 -> split q/k planes; seg2 -> v written TRANSPOSED
//        (fp16) into C3h=[B,HDIM,SEQ], bias folded.
// Terms:  NT=1: hh.  NT=2: hh+hl.  NT=3: hh+hl+lh.
//         NT=23: QKV fused — q/k segs 3-term, v seg 1-term.
// ---------------------------------------------------------------------------
template <int EPI, int NT>
__global__ void __launch_bounds__(256, 2) hfs_gemm(
    const hf* __restrict__ Ah, const hf* __restrict__ Al,
    const hf* __restrict__ Bh, const hf* __restrict__ Bl,
    const float* __restrict__ bias0, const float* __restrict__ bias1,
    const float* __restrict__ bias2,
    float* __restrict__ Cf,
    hf* __restrict__ Ch, hf* __restrict__ Cl,
    hf* __restrict__ C2h, hf* __restrict__ C2l,
    hf* __restrict__ C3h, hf* __restrict__ C3l,
    int M, int N, int Kloop, int lda, int ldb, int ldc,
    int nsplit,
    long long sA, long long sB, long long sC,
    long long kOffA, long long kOffB, long long sSplit)
{
    extern __shared__ uint32_t smem[];

    const int bz = blockIdx.z;
    const int batch = bz / nsplit;
    const int split = bz - batch * nsplit;

    Ah += (long long)batch * sA + split * kOffA;
    Al += (long long)batch * sA + split * kOffA;
    Bh += (long long)batch * sB + split * kOffB;
    Bl += (long long)batch * sB + split * kOffB;
    if (EPI == 0) Cf += (long long)batch * sC + split * sSplit;

    const int tid  = threadIdx.x;
    const int lane = tid & 31;
    const int warp = tid >> 5;
    const int bm = blockIdx.y * 128;
    const int bn = blockIdx.x * 128;
    const int wm = (warp & 1) * 64;
    const int wn = (warp >> 1) * 32;
    const int r = lane >> 2;
    const int c = lane & 3;

    const int seg = (EPI == 2) ? (bn / 768) : 0;
    // term flags (CTA-uniform)
    const bool aLo = (NT == 3) || (NT == 23 && seg < 2);
    const bool bLo = (NT == 23) ? (seg < 2) : (NT >= 2);

    // ---- loader mapping: thread -> row=tid/2, two 16B chunks per plane ----
    const int ld_row = tid >> 1;
    const int ld_c0  = (tid & 1) * 2;
    const hf* pAh = Ah + (long long)(bm + ld_row) * lda + ld_c0 * 8;
    const hf* pAl = Al + (long long)(bm + ld_row) * lda + ld_c0 * 8;
    const hf* pBh = Bh + (long long)(bn + ld_row) * ldb + ld_c0 * 8;
    const hf* pBl = Bl + (long long)(bn + ld_row) * ldb + ld_c0 * 8;

    uint32_t smem_u32;
    asm("{ .reg .u64 t; cvta.to.shared.u64 t, %1; cvt.u32.u64 %0, t; }"
        : "=r"(smem_u32) : "l"(smem));
    const uint32_t dst_base = smem_u32 + (ld_row * RSTRIDE + 4 * ld_c0) * 4;

    auto load_stage = [&](int stage, int k0) {
        const uint32_t d = dst_base + stage * STAGE_B;
        cpa16(d,                pAh + k0);
        cpa16(d + 16,           pAh + k0 + 8);
        if (aLo) {
            cpa16(d + PLANE_B,      pAl + k0);
            cpa16(d + PLANE_B + 16, pAl + k0 + 8);
        }
        cpa16(d + 2 * PLANE_B,      pBh + k0);
        cpa16(d + 2 * PLANE_B + 16, pBh + k0 + 8);
        if (bLo) {
            cpa16(d + 3 * PLANE_B,      pBl + k0);
            cpa16(d + 3 * PLANE_B + 16, pBl + k0 + 8);
        }
    };

    const uint32_t aOff = (((wm + (lane & 15)) * RSTRIDE + ((lane >> 4) << 2)) << 2);
    const uint32_t bOff = (((wn + (lane & 7) + ((lane >> 4) << 3)) * RSTRIDE
                            + (((lane >> 3) & 1) << 2)) << 2);

    float acc[4][4][4];
    #pragma unroll
    for (int i = 0; i < 4; i++)
        #pragma unroll
        for (int j = 0; j < 4; j++)
            #pragma unroll
            for (int e = 0; e < 4; e++) acc[i][j][e] = 0.f;

    const int T = Kloop / 32;

    load_stage(0, 0);  cpa_commit();
    if (T > 1) load_stage(1, 32);
    cpa_commit();

    for (int t = 0; t < T; t++) {
        cpa_wait<1>();
        __syncthreads();

        const uint32_t stage_base = smem_u32 + (t & 1) * STAGE_B;
        const uint32_t aBaseH = stage_base + aOff;
        const uint32_t aBaseL = aBaseH + PLANE_B;
        const uint32_t bBaseH = stage_base + 2 * PLANE_B + bOff;
        const uint32_t bBaseL = bBaseH + PLANE_B;

        #pragma unroll
        for (int ks = 0; ks < 2; ks++) {
            const uint32_t kb = ks * 32;
            uint32_t aH[4][4], aL[4][4], bH[4][2], bL[4][2];
            #pragma unroll
            for (int mi = 0; mi < 4; mi++) {
                ldsm_x4(aH[mi], aBaseH + mi * (16 * RSTRIDE * 4) + kb);
                if (aLo)
                    ldsm_x4(aL[mi], aBaseL + mi * (16 * RSTRIDE * 4) + kb);
            }
            #pragma unroll
            for (int np = 0; np < 2; np++) {
                uint32_t th[4];
                ldsm_x4(th, bBaseH + np * (16 * RSTRIDE * 4) + kb);
                bH[2*np][0] = th[0]; bH[2*np][1] = th[1];
                bH[2*np+1][0] = th[2]; bH[2*np+1][1] = th[3];
                if (bLo) {
                    uint32_t tl[4];
                    ldsm_x4(tl, bBaseL + np * (16 * RSTRIDE * 4) + kb);
                    bL[2*np][0] = tl[0]; bL[2*np][1] = tl[1];
                    bL[2*np+1][0] = tl[2]; bL[2*np+1][1] = tl[3];
                }
            }
            #pragma unroll
            for (int mi = 0; mi < 4; mi++)
                #pragma unroll
                for (int ni = 0; ni < 4; ni++) {
                    mma16816(acc[mi][ni], aH[mi], bH[ni]);
                    if (bLo) mma16816(acc[mi][ni], aH[mi], bL[ni]);
                    if (aLo) mma16816(acc[mi][ni], aL[mi], bH[ni]);
                }
        }
        __syncthreads();

        if (t + 2 < T) load_stage(t & 1, (t + 2) * 32);
        cpa_commit();
    }

    // ---------------- epilogue ----------------
    const float* bias = bias0;
    hf* dh = Ch; hf* dl = Cl;
    int cb = bn;
    int stride = ldc;
    if (EPI == 2) {
        cb = bn - seg * 768;
        stride = 768;
        if (seg == 1) { bias = bias1; dh = C2h; dl = C2l; }
        else if (seg == 2) { bias = bias2; }
    }

    if (EPI == 2 && seg == 2) {
        // ---- v segment: bias + fp16, written TRANSPOSED into C3h[B,HDIM,SEQ]
        __syncthreads();   // all warps done with pipeline smem (LDSM complete)
        hf* st = reinterpret_cast<hf*>(smem);
        #pragma unroll
        for (int mi = 0; mi < 4; mi++)
            #pragma unroll
            for (int ni = 0; ni < 4; ni++) {
                const int rl = wm + mi * 16 + r;
                const int cl = wn + ni * 8 + 2 * c;
                const float b0 = bias[cb + cl], b1 = bias[cb + cl + 1];
                st[cl * 136 + rl]           = __float2half(acc[mi][ni][0] + b0);
                st[(cl + 1) * 136 + rl]     = __float2half(acc[mi][ni][1] + b1);
                st[cl * 136 + rl + 8]       = __float2half(acc[mi][ni][2] + b0);
                st[(cl + 1) * 136 + rl + 8] = __float2half(acc[mi][ni][3] + b1);
            }
        __syncthreads();
        const int b  = bm >> 11;          // batch (SEQ = 2048)
        const int s0 = bm & 2047;         // seq offset within batch
        const int col   = tid >> 1;       // 0..127 local h
        const int chunk = tid & 1;        // 64-row half
        const uint4* src = reinterpret_cast<const uint4*>(st + col * 136 + chunk * 64);
        uint4* dst = reinterpret_cast<uint4*>(
            C3h + ((long long)b * HDIM + cb + col) * SEQ + s0 + chunk * 64);
        #pragma unroll
        for (int i = 0; i < 8; i++) dst[i] = src[i];
        return;
    }

    #pragma unroll
    for (int mi = 0; mi < 4; mi++)
        #pragma unroll
        for (int ni = 0; ni < 4; ni++) {
            const int row = bm + wm + mi * 16 + r;
            const int col = cb + wn + ni * 8 + 2 * c;
            float v00 = acc[mi][ni][0], v01 = acc[mi][ni][1];
            float v10 = acc[mi][ni][2], v11 = acc[mi][ni][3];
            if (bias) {
                const float b0 = bias[col], b1 = bias[col + 1];
                v00 += b0; v01 += b1; v10 += b0; v11 += b1;
            }
            if (EPI == 0) {
                *reinterpret_cast<float2*>(Cf + (long long)row * stride + col)
                    = make_float2(v00, v01);
                *reinterpret_cast<float2*>(Cf + (long long)(row + 8) * stride + col)
                    = make_float2(v10, v11);
            } else {
                hf h0, l0, h1, l1;
                split1(v00, h0, l0); split1(v01, h1, l1);
                *reinterpret_cast<__half2*>(dh + (long long)row * stride + col)
                    = __halves2half2(h0, h1);
                *reinterpret_cast<__half2*>(dl + (long long)row * stride + col)
                    = __halves2half2(l0, l1);
                split1(v10, h0, l0); split1(v11, h1, l1);
                *reinterpret_cast<__half2*>(dh + (long long)(row + 8) * stride + col)
                    = __halves2half2(h0, h1);
                *reinterpret_cast<__half2*>(dl + (long long)(row + 8) * stride + col)
                    = __halves2half2(l0, l1);
            }
        }
}

// ---------------------------------------------------------------------------
// All input splits in ONE launch. grid.y selects the segment.
// ---------------------------------------------------------------------------
__global__ void __launch_bounds__(256) split_all(
    const float* __restrict__ x,  const float* __restrict__ wq,
    const float* __restrict__ wk, const float* __restrict__ wv,
    const float* __restrict__ wo,
    hf* __restrict__ xh, hf* __restrict__ xl,
    hf* __restrict__ wch, hf* __restrict__ wcl,
    hf* __restrict__ woh, hf* __restrict__ wol)
{
    const float* in; hf *h, *l; int n4;
    switch (blockIdx.y) {
        case 0: in = x;  h = xh;            l = xl;            n4 = MTOT * NDIM / 4; break;
        case 1: in = wq; h = wch;           l = wcl;           n4 = WSZ / 4; break;
        case 2: in = wk; h = wch + WSZ;     l = wcl + WSZ;     n4 = WSZ / 4; break;
        case 3: in = wv; h = wch + 2 * WSZ; l = wcl + 2 * WSZ; n4 = WSZ / 4; break;
        default:in = wo; h = woh;           l = wol;           n4 = WSZ / 4; break;
    }
    for (int i = blockIdx.x * blockDim.x + threadIdx.x; i < n4;
         i += gridDim.x * blockDim.x) {
        float4 v = reinterpret_cast<const float4*>(in)[i];
        hf h0,l0,h1,l1,h2,l2,h3,l3;
        split1(v.x, h0, l0); split1(v.y, h1, l1);
        split1(v.z, h2, l2); split1(v.w, h3, l3);
        reinterpret_cast<__half2*>(h)[2 * i]     = __halves2half2(h0, h1);
        reinterpret_cast<__half2*>(h)[2 * i + 1] = __halves2half2(h2, h3);
        reinterpret_cast<__half2*>(l)[2 * i]     = __halves2half2(l0, l1);
        reinterpret_cast<__half2*>(l)[2 * i + 1] = __halves2half2(l2, l3);
    }
}

// ---------------------------------------------------------------------------
// combine split-K partials -> single fp16 plane (y hi)
// ---------------------------------------------------------------------------
__global__ void __launch_bounds__(256) combine_h(
    const float* __restrict__ p0, const float* __restrict__ p1,
    hf* __restrict__ h, int n4)
{
    for (int i = blockIdx.x * blockDim.x + threadIdx.x; i < n4;
         i += gridDim.x * blockDim.x) {
        float4 a = reinterpret_cast<const float4*>(p0)[i];
        float4 b = reinterpret_cast<const float4*>(p1)[i];
        a.x += b.x; a.y += b.y; a.z += b.z; a.w += b.w;
        reinterpret_cast<__half2*>(h)[2 * i]     = __floats2half2_rn(a.x, a.y);
        reinterpret_cast<__half2*>(h)[2 * i + 1] = __floats2half2_rn(a.z, a.w);
    }
}

// ---------------------------------------------------------------------------
// Row softmax: fp32 scores -> fp16 probs
// ---------------------------------------------------------------------------
__global__ void __launch_bounds__(256) softmax_h(
    const float* __restrict__ S, hf* __restrict__ Ph)
{
    __shared__ float buf[SEQ];
    __shared__ float red[8];

    const int tid = threadIdx.x;
    const float2* row2 = reinterpret_cast<const float2*>(S + (long long)blockIdx.x * SEQ);
    float2* b2 = reinterpret_cast<float2*>(buf);

    float m = -1e30f;
    #pragma unroll
    for (int j = 0; j < 4; j++) {
        float2 f = row2[tid + j * 256];
        b2[tid + j * 256] = f;
        m = fmaxf(m, fmaxf(f.x, f.y));
    }
    #pragma unroll
    for (int o = 16; o > 0; o >>= 1)
        m = fmaxf(m, __shfl_xor_sync(0xffffffffu, m, o));
    if ((tid & 31) == 0) red[tid >> 5] = m;
    __syncthreads();
    float bmax = red[0];
    #pragma unroll
    for (int w = 1; w < 8; w++) bmax = fmaxf(bmax, red[w]);
    __syncthreads();

    float s = 0.f;
    #pragma unroll
    for (int j = 0; j < 4; j++) {
        float2 f = b2[tid + j * 256];
        f.x = __expf(f.x - bmax);
        f.y = __expf(f.y - bmax);
        b2[tid + j * 256] = f;
        s += f.x + f.y;
    }
    #pragma unroll
    for (int o = 16; o > 0; o >>= 1)
        s += __shfl_xor_sync(0xffffffffu, s, o);
    if ((tid & 31) == 0) red[tid >> 5] = s;
    __syncthreads();
    float tot = 0.f;
    #pragma unroll
    for (int w = 0; w < 8; w++) tot += red[w];
    const float inv = 1.f / tot;

    __half2* ph2 = reinterpret_cast<__half2*>(Ph) + (long long)blockIdx.x * (SEQ / 2);
    #pragma unroll
    for (int j = 0; j < 4; j++) {
        float2 f = b2[tid + j * 256];
        ph2[tid + j * 256] = __floats2half2_rn(f.x * inv, f.y * inv);
    }
}

// ---------------------------------------------------------------------------
extern "C" void kernel_launch(void* const* d_in, const int* in_sizes, int n_in,
                              void* d_out, int out_size)
{
    const float* x  = (const float*)d_in[0];
    const float* wq = (const float*)d_in[1];
    const float* bq = (const float*)d_in[2];
    const float* wk = (const float*)d_in[3];
    const float* bk = (const float*)d_in[4];
    const float* wv = (const float*)d_in[5];
    const float* bv = (const float*)d_in[6];
    const float* wo = (const float*)d_in[7];
    const float* bo = (const float*)d_in[8];
    float* out = (float*)d_out;

    static bool attr_done = false;
    if (!attr_done) {
        cudaFuncSetAttribute((hfs_gemm<0,3>),  cudaFuncAttributeMaxDynamicSharedMemorySize, SMEM_BYTES);
        cudaFuncSetAttribute((hfs_gemm<0,1>),  cudaFuncAttributeMaxDynamicSharedMemorySize, SMEM_BYTES);
        cudaFuncSetAttribute((hfs_gemm<2,23>), cudaFuncAttributeMaxDynamicSharedMemorySize, SMEM_BYTES);
        attr_done = true;
    }

    hf *xh,*xl,*wch,*wcl,*woh,*wol;
    hf *qh,*ql,*kh,*kl,*vth,*sh,*yh;
    float *s, *py;
    cudaGetSymbolAddress((void**)&xh, g_xh);   cudaGetSymbolAddress((void**)&xl, g_xl);
    cudaGetSymbolAddress((void**)&wch, g_wch); cudaGetSymbolAddress((void**)&wcl, g_wcl);
    cudaGetSymbolAddress((void**)&woh, g_woh); cudaGetSymbolAddress((void**)&wol, g_wol);
    cudaGetSymbolAddress((void**)&qh, g_qh);   cudaGetSymbolAddress((void**)&ql, g_ql);
    cudaGetSymbolAddress((void**)&kh, g_kh);   cudaGetSymbolAddress((void**)&kl, g_kl);
    cudaGetSymbolAddress((void**)&vth, g_vth);
    cudaGetSymbolAddress((void**)&s, g_s);
    cudaGetSymbolAddress((void**)&sh, g_sh);
    cudaGetSymbolAddress((void**)&yh, g_yh);
    cudaGetSymbolAddress((void**)&py, g_py);

    const dim3 blk(256);

    // 0) all splits in one launch
    {
        dim3 grid(512, 5, 1);
        split_all<<<grid, blk>>>(x, wq, wk, wv, wo, xh, xl, wch, wcl, woh, wol);
    }

    // 1) fused QKV projection (q,k 3-term; v 1-term written transposed to vth)
    {
        dim3 grid(3 * HDIM / 128, MTOT / 128, 1);
        hfs_gemm<2,23><<<grid, blk, SMEM_BYTES>>>(
            xh, xl, wch, wcl, bq, bk, bv,
            nullptr, qh, ql, kh, kl, vth, vth,
            MTOT, 3 * HDIM, NDIM, NDIM, NDIM, HDIM, 1, 0, 0, 0, 0, 0, 0);
    }

    // 2) scores = Q K^T (fp32, 3-term)
    {
        dim3 grid(SEQ / 128, SEQ / 128, BATCH);
        hfs_gemm<0,3><<<grid, blk, SMEM_BYTES>>>(
            qh, ql, kh, kl, nullptr, nullptr, nullptr,
            s, nullptr, nullptr, nullptr, nullptr, nullptr, nullptr,
            SEQ, SEQ, HDIM, HDIM, HDIM, SEQ, 1,
            (long long)SEQ * HDIM, (long long)SEQ * HDIM, (long long)SEQ * SEQ,
            0, 0, 0);
    }

    // 3) softmax -> fp16 probs
    softmax_h<<<BATCH * SEQ, blk>>>(s, sh);

    // 4) y = P V  (1-term: P fp16 x V^T fp16; split-K=2)
    {
        dim3 grid(HDIM / 128, SEQ / 128, BATCH * 2);
        hfs_gemm<0,1><<<grid, blk, SMEM_BYTES>>>(
            sh, sh, vth, vth, nullptr, nullptr, nullptr,
            py, nullptr, nullptr, nullptr, nullptr, nullptr, nullptr,
            SEQ, HDIM, SEQ / 2, SEQ, SEQ, HDIM, 2,
            (long long)SEQ * SEQ, (long long)HDIM * SEQ, (long long)SEQ * HDIM,
            SEQ / 2, SEQ / 2, (long long)MTOT * HDIM);
    }
    combine_h<<<512, blk>>>(py, py + (long long)MTOT * HDIM, yh, MTOT * HDIM / 4);

    // 5) out = Y Wo^T + bo (1-term, no split-K, bias folded, direct fp32 write)
    {
        dim3 grid(NDIM / 128, MTOT / 128, 1);
        hfs_gemm<0,1><<<grid, blk, SMEM_BYTES>>>(
            yh, yh, woh, woh, bo, nullptr, nullptr,
            out, nullptr, nullptr, nullptr, nullptr, nullptr, nullptr,
            MTOT, NDIM, HDIM, HDIM, HDIM, NDIM, 1,
            0, 0, 0, 0, 0, 0);
    }
}